// round 15
// baseline (speedup 1.0000x reference)
// R14 theory (kept as comments; the whole reply is this single cuda block).
//
// R13 post-mortem: double-buffering gained only 81 us (9,297 -> 9,216)
// vs predicted ~1,000. Model was wrong: the GEMM mainloop was not
// sync-latency-bound within a CTA. Revised model: with 256 threads/CTA and
// ~39-55 KB smem/CTA, if ptxas picked >128 regs/thread only ONE CTA fits
// per SM (256 threads = 12.5% occupancy). Then every __syncthreads and
// every DRAM-latency bubble (weights stream from DRAM, ~600 cyc) stalls
// the whole SM with no co-resident CTA to fill issue slots. That would
// explain the estimated ~60% tensor-path efficiency.
//
// This round: ONE change - force 2 CTAs/SM on all four tensor-core kernels
// (gemm_tc both BN variants, scores_tc, av_tc) via __launch_bounds__(256,2).
// smem fits (2x38.9 KB / 2x55.3 KB / 2x53.2 KB of 228 KB). Register
// estimate for the largest (BN=128) path is ~116 regs, under the 128 cap,
// so spill risk is low (unlike R7, where the whole kernel changed at once
// and the cause of the regression was confounded).
//
// Prediction: if occupancy was the limiter, dur_us 9,216 -> ~7,800-8,400;
// if already 2 CTAs resident, neutral (~9,200); if BN=128 spills, mild
// regression on wi/logits only. rel_err unchanged at ~1.97e-5.

#include <cuda_runtime.h>
#include <cuda_bf16.h>
#include <math.h>

#define CL   12
#define CH   12
#define CDK  64
#define CDM  768
#define CDFF 3072
#define CV   32128
#define CB   2
#define CS   512
#define CT   512
#define NROWS (CB*CS)
#define NEGV (-1e9f)

// ------------------------- device scratch (static, no allocation) ---------
__device__ __align__(16) float g_x  [NROWS*CDM];
__device__ __align__(16) float g_h  [NROWS*CDM];
__device__ __align__(16) float g_qkv[3*NROWS*CDM];
__device__ __align__(16) float g_o  [NROWS*CDM];
__device__ __align__(16) float g_mem[NROWS*CDM];
__device__ __align__(16) float g_ff [NROWS*CDFF];
__device__ __align__(16) float g_sc [(size_t)CB*CH*CS*CS];
__device__ __align__(16) float g_bacc[CB*CS];
__device__ __align__(16) float g_pm  [CB*CS];

// ------------------------- rel-position buckets (exact thresholds) --------
__device__ __forceinline__ int bucket_bi(int q, int k) {
    int n = q - k; int ret = 0;
    if (n < 0) { ret = 16; n = -n; }
    if (n < 8) return ret + n;
    int b;
    if      (n < 12) b = 8;
    else if (n < 16) b = 9;
    else if (n < 23) b = 10;
    else if (n < 32) b = 11;
    else if (n < 46) b = 12;
    else if (n < 64) b = 13;
    else if (n < 91) b = 14;
    else             b = 15;
    return ret + b;
}
__device__ __forceinline__ int bucket_uni(int q, int k) {
    int n = q - k; if (n <= 0) return 0;
    if (n < 16) return n;
    if (n < 19)  return 16;
    if (n < 21)  return 17;
    if (n < 24)  return 18;
    if (n < 27)  return 19;
    if (n < 31)  return 20;
    if (n < 35)  return 21;
    if (n < 40)  return 22;
    if (n < 46)  return 23;
    if (n < 52)  return 24;
    if (n < 59)  return 25;
    if (n < 67)  return 26;
    if (n < 77)  return 27;
    if (n < 87)  return 28;
    if (n < 99)  return 29;
    if (n < 113) return 30;
    return 31;
}

// ------------------------- tensor-core helpers ----------------------------
__device__ __forceinline__ void ldsm4(unsigned* r, const void* p) {
    unsigned a = (unsigned)__cvta_generic_to_shared(p);
    asm volatile("ldmatrix.sync.aligned.m8n8.x4.shared.b16 {%0,%1,%2,%3}, [%4];"
        : "=r"(r[0]), "=r"(r[1]), "=r"(r[2]), "=r"(r[3]) : "r"(a));
}
__device__ __forceinline__ void ldsm4t(unsigned* r, const void* p) {
    unsigned a = (unsigned)__cvta_generic_to_shared(p);
    asm volatile("ldmatrix.sync.aligned.m8n8.x4.trans.shared.b16 {%0,%1,%2,%3}, [%4];"
        : "=r"(r[0]), "=r"(r[1]), "=r"(r[2]), "=r"(r[3]) : "r"(a));
}
__device__ __forceinline__ void mma16816(float* c, const unsigned* a, unsigned b0, unsigned b1) {
    asm volatile("mma.sync.aligned.m16n8k16.row.col.f32.bf16.bf16.f32 "
        "{%0,%1,%2,%3}, {%4,%5,%6,%7}, {%8,%9}, {%0,%1,%2,%3};"
        : "+f"(c[0]), "+f"(c[1]), "+f"(c[2]), "+f"(c[3])
        : "r"(a[0]), "r"(a[1]), "r"(a[2]), "r"(a[3]), "r"(b0), "r"(b1));
}
__device__ __forceinline__ void splt(float x, __nv_bfloat16& h, __nv_bfloat16& l) {
    h = __float2bfloat16_rn(x);
    l = __float2bfloat16_rn(x - __bfloat162float(h));
}

// ------------------------- split-bf16 tensor GEMM (double-buffered) -------
// C[M,N] = A[M,K] * B (+C)(ReLU). A,B,C fp32. NT: B is [N,K] row-major.
// BM=64, BK=32, 256 threads (8 warps: 4 m-groups x 2 n-groups), 2 CTAs/SM.
template<int BN, bool NT, bool ADD, bool RELU, bool BATCH>
__global__ void __launch_bounds__(256,2) gemm_tc(
    const float* __restrict__ A0, const float* __restrict__ A1,
    const float* __restrict__ Bb, long bStride,
    float* __restrict__ Cb, long cStride,
    int M, int N, int K)
{
    constexpr int LDA = 40;
    constexpr int LDB = BN + 8;
    constexpr int NT8 = BN / 16;
    constexpr int PB  = BN / 32;

    __shared__ __align__(16) __nv_bfloat16 Ah[2][64*LDA], Al[2][64*LDA];
    __shared__ __align__(16) __nv_bfloat16 Bh[2][32*LDB], Bl[2][32*LDB];

    const int tid  = threadIdx.x;
    const int z    = BATCH ? blockIdx.z : 0;
    const float* A = (BATCH && z > 0) ? A1 : A0;
    const float* B = Bb + (size_t)z * bStride;
    float*       C = Cb + (size_t)z * cStride;
    const int m0 = blockIdx.y * 64;
    const int n0 = blockIdx.x * BN;
    const int nk = K >> 5;

    const int lane = tid & 31, w = tid >> 5;
    const int wm = w & 3, wn = w >> 2;
    const int arow = tid >> 3, ac = (tid & 7) << 2;

    float4 pa[2];
    float4 pb[PB];

    float acc[NT8][4];
#pragma unroll
    for (int i = 0; i < NT8; i++) { acc[i][0]=acc[i][1]=acc[i][2]=acc[i][3]=0.f; }

    auto loadg = [&](int kt) {
#pragma unroll
        for (int it = 0; it < 2; it++)
            pa[it] = *(const float4*)(A + (size_t)(m0 + arow + it*32) * K + kt*32 + ac);
        if (NT) {
#pragma unroll
            for (int it = 0; it < PB; it++) {
                int idx = tid + it*256;
                int n = idx >> 3, kq = (idx & 7) << 2;
                pb[it] = *(const float4*)(B + (size_t)(n0 + n) * K + kt*32 + kq);
            }
        } else {
#pragma unroll
            for (int it = 0; it < PB; it++) {
                int idx = tid + it*256;
                int br = idx / (BN/4), bc = (idx % (BN/4)) * 4;
                pb[it] = *(const float4*)(B + (size_t)(kt*32 + br) * N + n0 + bc);
            }
        }
    };
    auto stores = [&](int p) {
#pragma unroll
        for (int it = 0; it < 2; it++) {
            int row = arow + it*32;
            splt(pa[it].x, Ah[p][row*LDA+ac+0], Al[p][row*LDA+ac+0]);
            splt(pa[it].y, Ah[p][row*LDA+ac+1], Al[p][row*LDA+ac+1]);
            splt(pa[it].z, Ah[p][row*LDA+ac+2], Al[p][row*LDA+ac+2]);
            splt(pa[it].w, Ah[p][row*LDA+ac+3], Al[p][row*LDA+ac+3]);
        }
        if (NT) {
#pragma unroll
            for (int it = 0; it < PB; it++) {
                int idx = tid + it*256;
                int n = idx >> 3, kq = (idx & 7) << 2;
                float xs[4] = {pb[it].x, pb[it].y, pb[it].z, pb[it].w};
#pragma unroll
                for (int j = 0; j < 4; j++)
                    splt(xs[j], Bh[p][(kq+j)*LDB + n], Bl[p][(kq+j)*LDB + n]);
            }
        } else {
#pragma unroll
            for (int it = 0; it < PB; it++) {
                int idx = tid + it*256;
                int br = idx / (BN/4), bc = (idx % (BN/4)) * 4;
                splt(pb[it].x, Bh[p][br*LDB+bc+0], Bl[p][br*LDB+bc+0]);
                splt(pb[it].y, Bh[p][br*LDB+bc+1], Bl[p][br*LDB+bc+1]);
                splt(pb[it].z, Bh[p][br*LDB+bc+2], Bl[p][br*LDB+bc+2]);
                splt(pb[it].w, Bh[p][br*LDB+bc+3], Bl[p][br*LDB+bc+3]);
            }
        }
    };

    loadg(0);
    stores(0);
    __syncthreads();

    for (int kt = 0; kt < nk; kt++) {
        const int p = kt & 1;
        const bool more = (kt + 1 < nk);
        if (more) loadg(kt + 1);
#pragma unroll
        for (int kh = 0; kh < 2; kh++) {
            unsigned a_h[4], a_l[4];
            const int aoff = (wm*16 + (lane & 15)) * LDA + kh*16 + ((lane >> 4) << 3);
            ldsm4(a_h, &Ah[p][aoff]);
            ldsm4(a_l, &Al[p][aoff]);
            unsigned b_h[NT8*2], b_l[NT8*2];
#pragma unroll
            for (int t2 = 0; t2 < NT8/2; t2++) {
                const int boff = (kh*16 + (lane & 15)) * LDB
                               + wn*(BN/2) + t2*16 + ((lane >> 4) << 3);
                ldsm4t(&b_h[t2*4], &Bh[p][boff]);
                ldsm4t(&b_l[t2*4], &Bl[p][boff]);
            }
#pragma unroll
            for (int nt = 0; nt < NT8; nt++) mma16816(acc[nt], a_h, b_h[2*nt], b_h[2*nt+1]);
#pragma unroll
            for (int nt = 0; nt < NT8; nt++) mma16816(acc[nt], a_h, b_l[2*nt], b_l[2*nt+1]);
#pragma unroll
            for (int nt = 0; nt < NT8; nt++) mma16816(acc[nt], a_l, b_h[2*nt], b_h[2*nt+1]);
        }
        if (more) stores(p ^ 1);
        __syncthreads();
    }

    const int g = lane >> 2, qd = lane & 3;
#pragma unroll
    for (int nt = 0; nt < NT8; nt++) {
        const int col = n0 + wn*(BN/2) + nt*8 + qd*2;
        const int r0  = m0 + wm*16 + g;
        size_t i0 = (size_t)r0 * N + col;
        size_t i1 = i0 + (size_t)8 * N;
        float v0 = acc[nt][0], v1 = acc[nt][1], v2 = acc[nt][2], v3 = acc[nt][3];
        if (ADD) { v0 += C[i0]; v1 += C[i0+1]; v2 += C[i1]; v3 += C[i1+1]; }
        if (RELU) { v0 = fmaxf(v0,0.f); v1 = fmaxf(v1,0.f); v2 = fmaxf(v2,0.f); v3 = fmaxf(v3,0.f); }
        C[i0] = v0; C[i0+1] = v1; C[i1] = v2; C[i1+1] = v3;
    }
}

// ------------------------- bias (shared by score kernels) ------------------
template<int MODE>
__device__ __forceinline__ float score_bias(
    int qg, int kg, int hh, int slen, int tlen,
    const float* __restrict__ relb,
    const float* __restrict__ bacc, const float* __restrict__ pmf,
    int bOff, int enc_layer)
{
    if (MODE == 0) {
        if (enc_layer > 0 && qg == kg) return 0.f;
        return relb[bucket_bi(qg, kg) * CH + hh]
             + ((kg < slen) ? 0.f : NEGV)
             + bacc[bOff + qg] + bacc[bOff + kg];
    } else if (MODE == 1) {
        float tm;
        if (kg == 0 && qg >= tlen) tm = 0.f;
        else tm = ((kg < slen) ? 0.f : NEGV)
                + (((kg <= qg) && (kg >= qg - 128)) ? 0.f : NEGV);
        return relb[bucket_uni(qg, kg) * CH + hh] + tm;
    } else {
        return ((kg < slen) ? 0.f : NEGV) + pmf[bOff + kg];
    }
}

// ------------------------- tensor-core attention scores -------------------
template<int MODE>
__global__ void __launch_bounds__(256,2) scores_tc(
    const float* __restrict__ Q, const float* __restrict__ Km,
    float* __restrict__ Sc, const float* __restrict__ relb,
    const int* __restrict__ src_len, const int* __restrict__ tgt_len,
    const float* __restrict__ bacc, const float* __restrict__ pmf,
    int enc_layer)
{
    constexpr int LDA = 72, LDB = 136;
    __shared__ __align__(16) __nv_bfloat16 Ah[64*LDA], Al[64*LDA];
    __shared__ __align__(16) __nv_bfloat16 Bh[64*LDB], Bl[64*LDB];

    const int bh = blockIdx.z, b = bh / CH, hh = bh % CH;
    const int q0 = blockIdx.y * 64, k0 = blockIdx.x * 128;
    const int tid = threadIdx.x;
    const int lane = tid & 31, w = tid >> 5;
    const int wm = w & 3, wn = w >> 2;

#pragma unroll
    for (int it = 0; it < 4; it++) {
        int idx = tid + it*256;
        int row = idx >> 4, c = (idx & 15) << 2;
        float4 a = *(const float4*)(Q + (size_t)(b*CS + q0 + row) * CDM + hh*CDK + c);
        splt(a.x, Ah[row*LDA+c+0], Al[row*LDA+c+0]);
        splt(a.y, Ah[row*LDA+c+1], Al[row*LDA+c+1]);
        splt(a.z, Ah[row*LDA+c+2], Al[row*LDA+c+2]);
        splt(a.w, Ah[row*LDA+c+3], Al[row*LDA+c+3]);
    }
#pragma unroll
    for (int it = 0; it < 8; it++) {
        int idx = tid + it*256;
        int n = idx >> 4, c = (idx & 15) << 2;
        float4 kv = *(const float4*)(Km + (size_t)(b*CS + k0 + n) * CDM + hh*CDK + c);
        splt(kv.x, Bh[(c+0)*LDB + n], Bl[(c+0)*LDB + n]);
        splt(kv.y, Bh[(c+1)*LDB + n], Bl[(c+1)*LDB + n]);
        splt(kv.z, Bh[(c+2)*LDB + n], Bl[(c+2)*LDB + n]);
        splt(kv.w, Bh[(c+3)*LDB + n], Bl[(c+3)*LDB + n]);
    }
    __syncthreads();

    float acc[8][4];
#pragma unroll
    for (int i = 0; i < 8; i++) { acc[i][0]=acc[i][1]=acc[i][2]=acc[i][3]=0.f; }

#pragma unroll
    for (int kh = 0; kh < 4; kh++) {
        unsigned a_h[4], a_l[4];
        const int aoff = (wm*16 + (lane & 15)) * LDA + kh*16 + ((lane >> 4) << 3);
        ldsm4(a_h, &Ah[aoff]);
        ldsm4(a_l, &Al[aoff]);
        unsigned bhf[16], blf[16];
#pragma unroll
        for (int t2 = 0; t2 < 4; t2++) {
            const int boff = (kh*16 + (lane & 15)) * LDB
                           + wn*64 + t2*16 + ((lane >> 4) << 3);
            ldsm4t(&bhf[t2*4], &Bh[boff]);
            ldsm4t(&blf[t2*4], &Bl[boff]);
        }
#pragma unroll
        for (int nt = 0; nt < 8; nt++) mma16816(acc[nt], a_h, bhf[2*nt], bhf[2*nt+1]);
#pragma unroll
        for (int nt = 0; nt < 8; nt++) mma16816(acc[nt], a_h, blf[2*nt], blf[2*nt+1]);
#pragma unroll
        for (int nt = 0; nt < 8; nt++) mma16816(acc[nt], a_l, bhf[2*nt], bhf[2*nt+1]);
    }

    const int slen = src_len[b];
    const int tlen = (MODE == 1) ? tgt_len[b] : 0;
    const int bOff = b * CS;
    const int g = lane >> 2, qd = lane & 3;
#pragma unroll
    for (int nt = 0; nt < 8; nt++) {
        const int col = k0 + wn*64 + nt*8 + qd*2;
        const int r0  = q0 + wm*16 + g;
        const int r1  = r0 + 8;
        float* p0 = Sc + ((size_t)bh * CS + r0) * CS + col;
        float* p1 = Sc + ((size_t)bh * CS + r1) * CS + col;
        p0[0] = acc[nt][0] + score_bias<MODE>(r0, col,   hh, slen, tlen, relb, bacc, pmf, bOff, enc_layer);
        p0[1] = acc[nt][1] + score_bias<MODE>(r0, col+1, hh, slen, tlen, relb, bacc, pmf, bOff, enc_layer);
        p1[0] = acc[nt][2] + score_bias<MODE>(r1, col,   hh, slen, tlen, relb, bacc, pmf, bOff, enc_layer);
        p1[1] = acc[nt][3] + score_bias<MODE>(r1, col+1, hh, slen, tlen, relb, bacc, pmf, bOff, enc_layer);
    }
}

// ------------------------- tensor-core P @ V (double-buffered) ------------
__global__ void __launch_bounds__(256,2) av_tc(
    const float* __restrict__ P, const float* __restrict__ V, float* __restrict__ O)
{
    constexpr int LDA = 40, LDB = 72;
    __shared__ __align__(16) __nv_bfloat16 Ah[2][64*LDA], Al[2][64*LDA];
    __shared__ __align__(16) __nv_bfloat16 Bh[2][32*LDB], Bl[2][32*LDB];

    const int bh = blockIdx.y, b = bh / CH, hh = bh % CH;
    const int q0 = blockIdx.x * 64;
    const int tid = threadIdx.x;
    const int lane = tid & 31, w = tid >> 5;
    const int wm = w & 3, wn = w >> 2;
    const int arow = tid >> 3, ac = (tid & 7) << 2;
    const int brow = tid >> 4, bc = (tid & 15) << 2;

    float4 pa[2];
    float4 pb[2];
    float acc[4][4];
#pragma unroll
    for (int i = 0; i < 4; i++) { acc[i][0]=acc[i][1]=acc[i][2]=acc[i][3]=0.f; }

    auto loadg = [&](int kt) {
#pragma unroll
        for (int it = 0; it < 2; it++)
            pa[it] = *(const float4*)(P + ((size_t)bh*CS + q0 + arow + it*32) * CS + kt*32 + ac);
#pragma unroll
        for (int it = 0; it < 2; it++)
            pb[it] = *(const float4*)(V + (size_t)(b*CS + kt*32 + brow + it*16) * CDM + hh*CDK + bc);
    };
    auto stores = [&](int p) {
#pragma unroll
        for (int it = 0; it < 2; it++) {
            int row = arow + it*32;
            splt(pa[it].x, Ah[p][row*LDA+ac+0], Al[p][row*LDA+ac+0]);
            splt(pa[it].y, Ah[p][row*LDA+ac+1], Al[p][row*LDA+ac+1]);
            splt(pa[it].z, Ah[p][row*LDA+ac+2], Al[p][row*LDA+ac+2]);
            splt(pa[it].w, Ah[p][row*LDA+ac+3], Al[p][row*LDA+ac+3]);
        }
#pragma unroll
        for (int it = 0; it < 2; it++) {
            int row = brow + it*16;
            splt(pb[it].x, Bh[p][row*LDB+bc+0], Bl[p][row*LDB+bc+0]);
            splt(pb[it].y, Bh[p][row*LDB+bc+1], Bl[p][row*LDB+bc+1]);
            splt(pb[it].z, Bh[p][row*LDB+bc+2], Bl[p][row*LDB+bc+2]);
            splt(pb[it].w, Bh[p][row*LDB+bc+3], Bl[p][row*LDB+bc+3]);
        }
    };

    loadg(0);
    stores(0);
    __syncthreads();

    for (int kt = 0; kt < CS/32; kt++) {
        const int p = kt & 1;
        const bool more = (kt + 1 < CS/32);
        if (more) loadg(kt + 1);
#pragma unroll
        for (int kh = 0; kh < 2; kh++) {
            unsigned a_h[4], a_l[4];
            const int aoff = (wm*16 + (lane & 15)) * LDA + kh*16 + ((lane >> 4) << 3);
            ldsm4(a_h, &Ah[p][aoff]);
            ldsm4(a_l, &Al[p][aoff]);
            unsigned bhf[8], blf[8];
#pragma unroll
            for (int t2 = 0; t2 < 2; t2++) {
                const int boff = (kh*16 + (lane & 15)) * LDB
                               + wn*32 + t2*16 + ((lane >> 4) << 3);
                ldsm4t(&bhf[t2*4], &Bh[p][boff]);
                ldsm4t(&blf[t2*4], &Bl[p][boff]);
            }
#pragma unroll
            for (int nt = 0; nt < 4; nt++) mma16816(acc[nt], a_h, bhf[2*nt], bhf[2*nt+1]);
#pragma unroll
            for (int nt = 0; nt < 4; nt++) mma16816(acc[nt], a_h, blf[2*nt], blf[2*nt+1]);
#pragma unroll
            for (int nt = 0; nt < 4; nt++) mma16816(acc[nt], a_l, bhf[2*nt], bhf[2*nt+1]);
        }
        if (more) stores(p ^ 1);
        __syncthreads();
    }

    const int g = lane >> 2, qd = lane & 3;
#pragma unroll
    for (int nt = 0; nt < 4; nt++) {
        const int col = hh*CDK + wn*32 + nt*8 + qd*2;
        const size_t r0 = (size_t)(b*CS + q0 + wm*16 + g) * CDM + col;
        const size_t r1 = r0 + (size_t)8 * CDM;
        O[r0] = acc[nt][0]; O[r0+1] = acc[nt][1];
        O[r1] = acc[nt][2]; O[r1+1] = acc[nt][3];
    }
}

// ------------------------- softmax over rows of length 512 ----------------
__global__ void __launch_bounds__(256) softmax_kernel(float* __restrict__ Sc)
{
    __shared__ float sh[8];
    float* row = Sc + (size_t)blockIdx.x * CS;
    const int t = threadIdx.x;
    float v0 = row[t], v1 = row[t + 256];
    float m = fmaxf(v0, v1);
#pragma unroll
    for (int o = 16; o; o >>= 1) m = fmaxf(m, __shfl_xor_sync(0xffffffffu, m, o));
    if ((t & 31) == 0) sh[t >> 5] = m;
    __syncthreads();
    float bm = sh[t & 7];
#pragma unroll
    for (int o = 4; o; o >>= 1) bm = fmaxf(bm, __shfl_xor_sync(0xffffffffu, bm, o));
    float e0 = expf(v0 - bm), e1 = expf(v1 - bm);
    float s = e0 + e1;
#pragma unroll
    for (int o = 16; o; o >>= 1) s += __shfl_xor_sync(0xffffffffu, s, o);
    __syncthreads();
    if ((t & 31) == 0) sh[t >> 5] = s;
    __syncthreads();
    float ts = sh[t & 7];
#pragma unroll
    for (int o = 4; o; o >>= 1) ts += __shfl_xor_sync(0xffffffffu, ts, o);
    float inv = 1.f / ts;
    row[t] = e0 * inv; row[t + 256] = e1 * inv;
}

// ------------------------- RMSNorm (T5) -----------------------------------
__global__ void __launch_bounds__(256) rms_kernel(
    const float* __restrict__ x, const float* __restrict__ w,
    float* __restrict__ out, float scale)
{
    __shared__ float sh[8];
    const int row = blockIdx.x, t = threadIdx.x;
    const float* xr = x + (size_t)row * CDM;
    float v0 = xr[t], v1 = xr[t+256], v2 = xr[t+512];
    float s = v0*v0 + v1*v1 + v2*v2;
#pragma unroll
    for (int o = 16; o; o >>= 1) s += __shfl_xor_sync(0xffffffffu, s, o);
    if ((t & 31) == 0) sh[t >> 5] = s;
    __syncthreads();
    float ts = sh[t & 7];
#pragma unroll
    for (int o = 4; o; o >>= 1) ts += __shfl_xor_sync(0xffffffffu, ts, o);
    float inv = rsqrtf(ts * (1.0f/CDM) + 1e-6f) * scale;
    float* orow = out + (size_t)row * CDM;
    orow[t]     = v0 * inv * w[t];
    orow[t+256] = v1 * inv * w[t+256];
    orow[t+512] = v2 * inv * w[t+512];
}

// ------------------------- elementwise helpers ----------------------------
__global__ void __launch_bounds__(256) embed_gather(
    const float* __restrict__ embed, const int* __restrict__ tok,
    float* __restrict__ out)
{
    int idx = blockIdx.x * 256 + threadIdx.x;
    int r = idx / CDM, c = idx - r * CDM;
    out[idx] = embed[(size_t)tok[r] * CDM + c];
}

__global__ void zero_ch0(float* __restrict__ x)
{
    int r = blockIdx.x * 256 + threadIdx.x;
    if (r < NROWS) x[(size_t)r * CDM] = 0.f;
}

__global__ void init_bacc()
{
    int i = blockIdx.x * 256 + threadIdx.x;
    if (i < CB*CS) g_bacc[i] = 0.f;
}

__global__ void copy_k(const float* __restrict__ src, float* __restrict__ dst)
{
    int i = blockIdx.x * 256 + threadIdx.x;
    dst[i] = src[i];
}

// ------------------------- prune gate -------------------------------------
__global__ void __launch_bounds__(512) gate_kernel(
    const float* __restrict__ x, const float* __restrict__ gumbel,
    const int* __restrict__ src_len, const int* __restrict__ keep,
    float* __restrict__ out_pm, float* __restrict__ out_pp, int layer)
{
    const int b = blockIdx.x, s = threadIdx.x;
    float x0 = x[(size_t)(b*CS + s) * CDM];
    float z = (x0 + gumbel[(b*CL + layer) * CS + s] + 3.0f) * 2.0f;
    float ls = (z >= 0.f) ? -log1pf(expf(-z)) : (z - log1pf(expf(z)));
    float pm = ls + ((layer > 0) ? g_pm[b*CS + s] : 0.f);
    if (s == keep[b]) pm = 0.f;
    g_pm[b*CS + s] = pm;
    g_bacc[b*CS + s] += pm;
    out_pm[(b*CL + layer) * CS + s] = pm;
    out_pp[(b*CL + layer) * CS + s] = expf(pm * 0.125f) * ((s < src_len[b]) ? 1.f : 0.f);
}

// ------------------------- host orchestration -----------------------------
extern "C" void kernel_launch(void* const* d_in, const int* in_sizes, int n_in,
                              void* d_out, int out_size)
{
    const float* embed      = (const float*)d_in[0];
    const float* enc_ln     = (const float*)d_in[1];
    const float* enc_attn_w = (const float*)d_in[2];
    const float* enc_wi     = (const float*)d_in[3];
    const float* enc_wo     = (const float*)d_in[4];
    const float* enc_relb   = (const float*)d_in[5];
    const float* enc_fln    = (const float*)d_in[6];
    const float* dec_ln     = (const float*)d_in[7];
    const float* dec_self_w = (const float*)d_in[8];
    const float* dec_cross_w= (const float*)d_in[9];
    const float* dec_wi     = (const float*)d_in[10];
    const float* dec_wo     = (const float*)d_in[11];
    const float* dec_relb   = (const float*)d_in[12];
    const float* dec_fln    = (const float*)d_in[13];
    const float* gumbel     = (const float*)d_in[14];
    const int*   src_tok    = (const int*)d_in[15];
    const int*   src_len    = (const int*)d_in[16];
    const int*   tgt_tok    = (const int*)d_in[17];
    const int*   tgt_len    = (const int*)d_in[18];
    const int*   keep       = (const int*)d_in[19];

    float* out = (float*)d_out;
    float* out_mem = out;
    float* out_pm  = out + (size_t)CB*CS*CDM;
    float* out_pp  = out_pm + (size_t)CB*CL*CS;
    float* out_log = out_pp + (size_t)CB*CL*CS;

    float *x, *h, *qkv, *o, *mem, *ff, *sc, *bacc, *pm;
    cudaGetSymbolAddress((void**)&x,   g_x);
    cudaGetSymbolAddress((void**)&h,   g_h);
    cudaGetSymbolAddress((void**)&qkv, g_qkv);
    cudaGetSymbolAddress((void**)&o,   g_o);
    cudaGetSymbolAddress((void**)&mem, g_mem);
    cudaGetSymbolAddress((void**)&ff,  g_ff);
    cudaGetSymbolAddress((void**)&sc,  g_sc);
    cudaGetSymbolAddress((void**)&bacc,g_bacc);
    cudaGetSymbolAddress((void**)&pm,  g_pm);

    float* q = qkv;
    float* k = qkv + (size_t)NROWS*CDM;
    float* v = qkv + (size_t)2*NROWS*CDM;
    const long QS = (long)NROWS*CDM;
    const long WS = (long)CDM*CDM;

    const dim3 gQKV(CDM/64, NROWS/64, 3);
    const dim3 gPrj(CDM/64, NROWS/64);
    const dim3 gWi (CDFF/128, NROWS/64);
    const dim3 gLg (CV/128, NROWS/64);
    const dim3 gSc(CS/128, CS/64, CB*CH);
    const dim3 gAv(CS/64, CB*CH);
    const int  nSoft = CB*CH*CS;
    const float inv_sqrt_dm = 0.03608439182435161f;

    init_bacc<<<4, 256>>>();
    embed_gather<<<NROWS*CDM/256, 256>>>(embed, src_tok, x);

    // ---------------- encoder ----------------
    for (int i = 0; i < CL; i++) {
        const float* W = enc_attn_w + (size_t)i*4*CDM*CDM;
        zero_ch0<<<4, 256>>>(x);
        rms_kernel<<<NROWS, 256>>>(x, enc_ln + (size_t)(i*2+0)*CDM, h, 1.f);
        gemm_tc<64,false,false,false,true><<<gQKV, 256>>>(
            h, h, W, WS, qkv, QS, NROWS, CDM, CDM);
        scores_tc<0><<<gSc, 256>>>(q, k, sc, enc_relb, src_len, tgt_len, bacc, pm, i);
        softmax_kernel<<<nSoft, 256>>>(sc);
        av_tc<<<gAv, 256>>>(sc, v, o);
        gemm_tc<64,false,true,false,false><<<gPrj, 256>>>(
            o, o, W + 3*WS, 0, x, 0, NROWS, CDM, CDM);
        rms_kernel<<<NROWS, 256>>>(x, enc_ln + (size_t)(i*2+1)*CDM, h, 1.f);
        gemm_tc<128,false,false,true,false><<<gWi, 256>>>(
            h, h, enc_wi + (size_t)i*CDM*CDFF, 0, ff, 0, NROWS, CDFF, CDM);
        gemm_tc<64,false,true,false,false><<<gPrj, 256>>>(
            ff, ff, enc_wo + (size_t)i*CDFF*CDM, 0, x, 0, NROWS, CDM, CDFF);
        gate_kernel<<<CB, 512>>>(x, gumbel, src_len, keep, out_pm, out_pp, i);
    }
    rms_kernel<<<NROWS, 256>>>(x, enc_fln, mem, 1.f);
    copy_k<<<NROWS*CDM/256, 256>>>(mem, out_mem);

    // ---------------- decoder ----------------
    embed_gather<<<NROWS*CDM/256, 256>>>(embed, tgt_tok, x);
    for (int i = 0; i < CL; i++) {
        const float* Ws = dec_self_w  + (size_t)i*4*CDM*CDM;
        const float* Wc = dec_cross_w + (size_t)i*4*CDM*CDM;
        rms_kernel<<<NROWS, 256>>>(x, dec_ln + (size_t)(i*3+0)*CDM, h, 1.f);
        gemm_tc<64,false,false,false,true><<<gQKV, 256>>>(
            h, h, Ws, WS, qkv, QS, NROWS, CDM, CDM);
        scores_tc<1><<<gSc, 256>>>(q, k, sc, dec_relb, src_len, tgt_len, bacc, pm, 0);
        softmax_kernel<<<nSoft, 256>>>(sc);
        av_tc<<<gAv, 256>>>(sc, v, o);
        gemm_tc<64,false,true,false,false><<<gPrj, 256>>>(
            o, o, Ws + 3*WS, 0, x, 0, NROWS, CDM, CDM);
        rms_kernel<<<NROWS, 256>>>(x, dec_ln + (size_t)(i*3+1)*CDM, h, 1.f);
        gemm_tc<64,false,false,false,true><<<gQKV, 256>>>(
            h, mem, Wc, WS, qkv, QS, NROWS, CDM, CDM);
        scores_tc<2><<<gSc, 256>>>(q, k, sc, dec_relb, src_len, tgt_len, bacc, pm, 0);
        softmax_kernel<<<nSoft, 256>>>(sc);
        av_tc<<<gAv, 256>>>(sc, v, o);
        gemm_tc<64,false,true,false,false><<<gPrj, 256>>>(
            o, o, Wc + 3*WS, 0, x, 0, NROWS, CDM, CDM);
        rms_kernel<<<NROWS, 256>>>(x, dec_ln + (size_t)(i*3+2)*CDM, h, 1.f);
        gemm_tc<128,false,false,true,false><<<gWi, 256>>>(
            h, h, dec_wi + (size_t)i*CDM*CDFF, 0, ff, 0, NROWS, CDFF, CDM);
        gemm_tc<64,false,true,false,false><<<gPrj, 256>>>(
            ff, ff, dec_wo + (size_t)i*CDFF*CDM, 0, x, 0, NROWS, CDM, CDFF);
    }
    rms_kernel<<<NROWS, 256>>>(x, dec_fln, h, inv_sqrt_dm);
    gemm_tc<128,true,false,false,false><<<gLg, 256>>>(
        h, h, embed, 0, out_log, 0, NROWS, CV, CDM);
}

// round 16
// speedup vs baseline: 1.0191x; 1.0191x over previous
// R15 theory (comments only; whole reply is one cuda block).
//
// R14 post-mortem: forcing 2 CTAs/SM regressed slightly (9,216 -> 9,339).
// The 128-reg cap it implies most likely introduced spills in the BN=128
// variants; occupancy was NOT the GEMM limiter. Reverting launch bounds to
// plain (256); 9,216 (R13 double-buffered) stays the baseline design.
//
// New model of the GEMM mainloop cost: per k-step each thread executes
// 32 scalar STS.U16 stores (16 splt hi + 16 lo results written one bf16 at
// a time) = 16 KB of smem-store traffic per CTA per k-step issued as
// half-word stores, competing with LDSM reads on the 128 B/cyc smem port
// and bloating issue slots. The MMA work per k-step is only ~384 cyc, so
// the scalar STS phase is a meaningful serialized fraction.
//
// This round, ONE change: vectorize the split+store path. New splt2()
// converts two floats with __floats2bfloat162_rn and packs into uint32;
// stores become uint2 (STS.U64) on all layouts where the smem destination
// is contiguous and 8B-aligned (A tiles everywhere, B tiles in NN GEMMs,
// Q in scores_tc, P and V in av_tc). Strided destinations (NT logits B,
// transposed K in scores_tc) keep scalar stores. This cuts STS instruction
// count per k-step from 32 to ~12 per thread and halves the fp32->bf16
// convert instruction count (packed intrinsic).
//
// Prediction: dur_us 9,216 -> ~8,500-8,900; rel_err unchanged at 1.97e-5
// (identical rounding per element). If neutral, the smem-store phase was
// already fully hidden and the limiter is the HMMA issue rate itself ->
// next step would be tcgen05 conversion.

#include <cuda_runtime.h>
#include <cuda_bf16.h>
#include <math.h>

#define CL   12
#define CH   12
#define CDK  64
#define CDM  768
#define CDFF 3072
#define CV   32128
#define CB   2
#define CS   512
#define CT   512
#define NROWS (CB*CS)
#define NEGV (-1e9f)

// ------------------------- device scratch (static, no allocation) ---------
__device__ __align__(16) float g_x  [NROWS*CDM];
__device__ __align__(16) float g_h  [NROWS*CDM];
__device__ __align__(16) float g_qkv[3*NROWS*CDM];
__device__ __align__(16) float g_o  [NROWS*CDM];
__device__ __align__(16) float g_mem[NROWS*CDM];
__device__ __align__(16) float g_ff [NROWS*CDFF];
__device__ __align__(16) float g_sc [(size_t)CB*CH*CS*CS];
__device__ __align__(16) float g_bacc[CB*CS];
__device__ __align__(16) float g_pm  [CB*CS];

// ------------------------- rel-position buckets (exact thresholds) --------
__device__ __forceinline__ int bucket_bi(int q, int k) {
    int n = q - k; int ret = 0;
    if (n < 0) { ret = 16; n = -n; }
    if (n < 8) return ret + n;
    int b;
    if      (n < 12) b = 8;
    else if (n < 16) b = 9;
    else if (n < 23) b = 10;
    else if (n < 32) b = 11;
    else if (n < 46) b = 12;
    else if (n < 64) b = 13;
    else if (n < 91) b = 14;
    else             b = 15;
    return ret + b;
}
__device__ __forceinline__ int bucket_uni(int q, int k) {
    int n = q - k; if (n <= 0) return 0;
    if (n < 16) return n;
    if (n < 19)  return 16;
    if (n < 21)  return 17;
    if (n < 24)  return 18;
    if (n < 27)  return 19;
    if (n < 31)  return 20;
    if (n < 35)  return 21;
    if (n < 40)  return 22;
    if (n < 46)  return 23;
    if (n < 52)  return 24;
    if (n < 59)  return 25;
    if (n < 67)  return 26;
    if (n < 77)  return 27;
    if (n < 87)  return 28;
    if (n < 99)  return 29;
    if (n < 113) return 30;
    return 31;
}

// ------------------------- tensor-core helpers ----------------------------
__device__ __forceinline__ void ldsm4(unsigned* r, const void* p) {
    unsigned a = (unsigned)__cvta_generic_to_shared(p);
    asm volatile("ldmatrix.sync.aligned.m8n8.x4.shared.b16 {%0,%1,%2,%3}, [%4];"
        : "=r"(r[0]), "=r"(r[1]), "=r"(r[2]), "=r"(r[3]) : "r"(a));
}
__device__ __forceinline__ void ldsm4t(unsigned* r, const void* p) {
    unsigned a = (unsigned)__cvta_generic_to_shared(p);
    asm volatile("ldmatrix.sync.aligned.m8n8.x4.trans.shared.b16 {%0,%1,%2,%3}, [%4];"
        : "=r"(r[0]), "=r"(r[1]), "=r"(r[2]), "=r"(r[3]) : "r"(a));
}
__device__ __forceinline__ void mma16816(float* c, const unsigned* a, unsigned b0, unsigned b1) {
    asm volatile("mma.sync.aligned.m16n8k16.row.col.f32.bf16.bf16.f32 "
        "{%0,%1,%2,%3}, {%4,%5,%6,%7}, {%8,%9}, {%0,%1,%2,%3};"
        : "+f"(c[0]), "+f"(c[1]), "+f"(c[2]), "+f"(c[3])
        : "r"(a[0]), "r"(a[1]), "r"(a[2]), "r"(a[3]), "r"(b0), "r"(b1));
}
__device__ __forceinline__ void splt(float x, __nv_bfloat16& h, __nv_bfloat16& l) {
    h = __float2bfloat16_rn(x);
    l = __float2bfloat16_rn(x - __bfloat162float(h));
}
// packed split: two floats -> packed hi bf16x2 and lo bf16x2 (same rounding
// per element as splt, so numerics are bit-identical to previous rounds)
__device__ __forceinline__ void splt2(float a, float b, unsigned& h, unsigned& l) {
    __nv_bfloat162 hh = __floats2bfloat162_rn(a, b);
    float la = a - __bfloat162float(__low2bfloat16(hh));
    float lb = b - __bfloat162float(__high2bfloat16(hh));
    __nv_bfloat162 ll = __floats2bfloat162_rn(la, lb);
    h = *reinterpret_cast<unsigned*>(&hh);
    l = *reinterpret_cast<unsigned*>(&ll);
}
// split a float4 into two uint2 (4 bf16 hi, 4 bf16 lo)
__device__ __forceinline__ void splt4(const float4& v, uint2& h, uint2& l) {
    splt2(v.x, v.y, h.x, l.x);
    splt2(v.z, v.w, h.y, l.y);
}

// ------------------------- split-bf16 tensor GEMM (double-buffered) -------
// C[M,N] = A[M,K] * B (+C)(ReLU). A,B,C fp32. NT: B is [N,K] row-major.
// BM=64, BK=32, 256 threads (8 warps: 4 m-groups x 2 n-groups).
template<int BN, bool NT, bool ADD, bool RELU, bool BATCH>
__global__ void __launch_bounds__(256) gemm_tc(
    const float* __restrict__ A0, const float* __restrict__ A1,
    const float* __restrict__ Bb, long bStride,
    float* __restrict__ Cb, long cStride,
    int M, int N, int K)
{
    constexpr int LDA = 40;
    constexpr int LDB = BN + 8;
    constexpr int NT8 = BN / 16;
    constexpr int PB  = BN / 32;

    __shared__ __align__(16) __nv_bfloat16 Ah[2][64*LDA], Al[2][64*LDA];
    __shared__ __align__(16) __nv_bfloat16 Bh[2][32*LDB], Bl[2][32*LDB];

    const int tid  = threadIdx.x;
    const int z    = BATCH ? blockIdx.z : 0;
    const float* A = (BATCH && z > 0) ? A1 : A0;
    const float* B = Bb + (size_t)z * bStride;
    float*       C = Cb + (size_t)z * cStride;
    const int m0 = blockIdx.y * 64;
    const int n0 = blockIdx.x * BN;
    const int nk = K >> 5;

    const int lane = tid & 31, w = tid >> 5;
    const int wm = w & 3, wn = w >> 2;
    const int arow = tid >> 3, ac = (tid & 7) << 2;

    float4 pa[2];
    float4 pb[PB];

    float acc[NT8][4];
#pragma unroll
    for (int i = 0; i < NT8; i++) { acc[i][0]=acc[i][1]=acc[i][2]=acc[i][3]=0.f; }

    auto loadg = [&](int kt) {
#pragma unroll
        for (int it = 0; it < 2; it++)
            pa[it] = *(const float4*)(A + (size_t)(m0 + arow + it*32) * K + kt*32 + ac);
        if (NT) {
#pragma unroll
            for (int it = 0; it < PB; it++) {
                int idx = tid + it*256;
                int n = idx >> 3, kq = (idx & 7) << 2;
                pb[it] = *(const float4*)(B + (size_t)(n0 + n) * K + kt*32 + kq);
            }
        } else {
#pragma unroll
            for (int it = 0; it < PB; it++) {
                int idx = tid + it*256;
                int br = idx / (BN/4), bc = (idx % (BN/4)) * 4;
                pb[it] = *(const float4*)(B + (size_t)(kt*32 + br) * N + n0 + bc);
            }
        }
    };
    auto stores = [&](int p) {
#pragma unroll
        for (int it = 0; it < 2; it++) {
            int row = arow + it*32;
            uint2 h4, l4;
            splt4(pa[it], h4, l4);
            *(uint2*)&Ah[p][row*LDA + ac] = h4;
            *(uint2*)&Al[p][row*LDA + ac] = l4;
        }
        if (NT) {
#pragma unroll
            for (int it = 0; it < PB; it++) {
                int idx = tid + it*256;
                int n = idx >> 3, kq = (idx & 7) << 2;
                float xs[4] = {pb[it].x, pb[it].y, pb[it].z, pb[it].w};
#pragma unroll
                for (int j = 0; j < 4; j++)
                    splt(xs[j], Bh[p][(kq+j)*LDB + n], Bl[p][(kq+j)*LDB + n]);
            }
        } else {
#pragma unroll
            for (int it = 0; it < PB; it++) {
                int idx = tid + it*256;
                int br = idx / (BN/4), bc = (idx % (BN/4)) * 4;
                uint2 h4, l4;
                splt4(pb[it], h4, l4);
                *(uint2*)&Bh[p][br*LDB + bc] = h4;
                *(uint2*)&Bl[p][br*LDB + bc] = l4;
            }
        }
    };

    loadg(0);
    stores(0);
    __syncthreads();

    for (int kt = 0; kt < nk; kt++) {
        const int p = kt & 1;
        const bool more = (kt + 1 < nk);
        if (more) loadg(kt + 1);
#pragma unroll
        for (int kh = 0; kh < 2; kh++) {
            unsigned a_h[4], a_l[4];
            const int aoff = (wm*16 + (lane & 15)) * LDA + kh*16 + ((lane >> 4) << 3);
            ldsm4(a_h, &Ah[p][aoff]);
            ldsm4(a_l, &Al[p][aoff]);
            unsigned b_h[NT8*2], b_l[NT8*2];
#pragma unroll
            for (int t2 = 0; t2 < NT8/2; t2++) {
                const int boff = (kh*16 + (lane & 15)) * LDB
                               + wn*(BN/2) + t2*16 + ((lane >> 4) << 3);
                ldsm4t(&b_h[t2*4], &Bh[p][boff]);
                ldsm4t(&b_l[t2*4], &Bl[p][boff]);
            }
#pragma unroll
            for (int nt = 0; nt < NT8; nt++) mma16816(acc[nt], a_h, b_h[2*nt], b_h[2*nt+1]);
#pragma unroll
            for (int nt = 0; nt < NT8; nt++) mma16816(acc[nt], a_h, b_l[2*nt], b_l[2*nt+1]);
#pragma unroll
            for (int nt = 0; nt < NT8; nt++) mma16816(acc[nt], a_l, b_h[2*nt], b_h[2*nt+1]);
        }
        if (more) stores(p ^ 1);
        __syncthreads();
    }

    const int g = lane >> 2, qd = lane & 3;
#pragma unroll
    for (int nt = 0; nt < NT8; nt++) {
        const int col = n0 + wn*(BN/2) + nt*8 + qd*2;
        const int r0  = m0 + wm*16 + g;
        size_t i0 = (size_t)r0 * N + col;
        size_t i1 = i0 + (size_t)8 * N;
        float v0 = acc[nt][0], v1 = acc[nt][1], v2 = acc[nt][2], v3 = acc[nt][3];
        if (ADD) { v0 += C[i0]; v1 += C[i0+1]; v2 += C[i1]; v3 += C[i1+1]; }
        if (RELU) { v0 = fmaxf(v0,0.f); v1 = fmaxf(v1,0.f); v2 = fmaxf(v2,0.f); v3 = fmaxf(v3,0.f); }
        C[i0] = v0; C[i0+1] = v1; C[i1] = v2; C[i1+1] = v3;
    }
}

// ------------------------- bias (shared by score kernels) ------------------
template<int MODE>
__device__ __forceinline__ float score_bias(
    int qg, int kg, int hh, int slen, int tlen,
    const float* __restrict__ relb,
    const float* __restrict__ bacc, const float* __restrict__ pmf,
    int bOff, int enc_layer)
{
    if (MODE == 0) {
        if (enc_layer > 0 && qg == kg) return 0.f;
        return relb[bucket_bi(qg, kg) * CH + hh]
             + ((kg < slen) ? 0.f : NEGV)
             + bacc[bOff + qg] + bacc[bOff + kg];
    } else if (MODE == 1) {
        float tm;
        if (kg == 0 && qg >= tlen) tm = 0.f;
        else tm = ((kg < slen) ? 0.f : NEGV)
                + (((kg <= qg) && (kg >= qg - 128)) ? 0.f : NEGV);
        return relb[bucket_uni(qg, kg) * CH + hh] + tm;
    } else {
        return ((kg < slen) ? 0.f : NEGV) + pmf[bOff + kg];
    }
}

// ------------------------- tensor-core attention scores -------------------
template<int MODE>
__global__ void __launch_bounds__(256) scores_tc(
    const float* __restrict__ Q, const float* __restrict__ Km,
    float* __restrict__ Sc, const float* __restrict__ relb,
    const int* __restrict__ src_len, const int* __restrict__ tgt_len,
    const float* __restrict__ bacc, const float* __restrict__ pmf,
    int enc_layer)
{
    constexpr int LDA = 72, LDB = 136;
    __shared__ __align__(16) __nv_bfloat16 Ah[64*LDA], Al[64*LDA];
    __shared__ __align__(16) __nv_bfloat16 Bh[64*LDB], Bl[64*LDB];

    const int bh = blockIdx.z, b = bh / CH, hh = bh % CH;
    const int q0 = blockIdx.y * 64, k0 = blockIdx.x * 128;
    const int tid = threadIdx.x;
    const int lane = tid & 31, w = tid >> 5;
    const int wm = w & 3, wn = w >> 2;

#pragma unroll
    for (int it = 0; it < 4; it++) {
        int idx = tid + it*256;
        int row = idx >> 4, c = (idx & 15) << 2;
        float4 a = *(const float4*)(Q + (size_t)(b*CS + q0 + row) * CDM + hh*CDK + c);
        uint2 h4, l4;
        splt4(a, h4, l4);
        *(uint2*)&Ah[row*LDA + c] = h4;
        *(uint2*)&Al[row*LDA + c] = l4;
    }
#pragma unroll
    for (int it = 0; it < 8; it++) {
        int idx = tid + it*256;
        int n = idx >> 4, c = (idx & 15) << 2;
        float4 kv = *(const float4*)(Km + (size_t)(b*CS + k0 + n) * CDM + hh*CDK + c);
        splt(kv.x, Bh[(c+0)*LDB + n], Bl[(c+0)*LDB + n]);
        splt(kv.y, Bh[(c+1)*LDB + n], Bl[(c+1)*LDB + n]);
        splt(kv.z, Bh[(c+2)*LDB + n], Bl[(c+2)*LDB + n]);
        splt(kv.w, Bh[(c+3)*LDB + n], Bl[(c+3)*LDB + n]);
    }
    __syncthreads();

    float acc[8][4];
#pragma unroll
    for (int i = 0; i < 8; i++) { acc[i][0]=acc[i][1]=acc[i][2]=acc[i][3]=0.f; }

#pragma unroll
    for (int kh = 0; kh < 4; kh++) {
        unsigned a_h[4], a_l[4];
        const int aoff = (wm*16 + (lane & 15)) * LDA + kh*16 + ((lane >> 4) << 3);
        ldsm4(a_h, &Ah[aoff]);
        ldsm4(a_l, &Al[aoff]);
        unsigned bhf[16], blf[16];
#pragma unroll
        for (int t2 = 0; t2 < 4; t2++) {
            const int boff = (kh*16 + (lane & 15)) * LDB
                           + wn*64 + t2*16 + ((lane >> 4) << 3);
            ldsm4t(&bhf[t2*4], &Bh[boff]);
            ldsm4t(&blf[t2*4], &Bl[boff]);
        }
#pragma unroll
        for (int nt = 0; nt < 8; nt++) mma16816(acc[nt], a_h, bhf[2*nt], bhf[2*nt+1]);
#pragma unroll
        for (int nt = 0; nt < 8; nt++) mma16816(acc[nt], a_h, blf[2*nt], blf[2*nt+1]);
#pragma unroll
        for (int nt = 0; nt < 8; nt++) mma16816(acc[nt], a_l, bhf[2*nt], bhf[2*nt+1]);
    }

    const int slen = src_len[b];
    const int tlen = (MODE == 1) ? tgt_len[b] : 0;
    const int bOff = b * CS;
    const int g = lane >> 2, qd = lane & 3;
#pragma unroll
    for (int nt = 0; nt < 8; nt++) {
        const int col = k0 + wn*64 + nt*8 + qd*2;
        const int r0  = q0 + wm*16 + g;
        const int r1  = r0 + 8;
        float* p0 = Sc + ((size_t)bh * CS + r0) * CS + col;
        float* p1 = Sc + ((size_t)bh * CS + r1) * CS + col;
        p0[0] = acc[nt][0] + score_bias<MODE>(r0, col,   hh, slen, tlen, relb, bacc, pmf, bOff, enc_layer);
        p0[1] = acc[nt][1] + score_bias<MODE>(r0, col+1, hh, slen, tlen, relb, bacc, pmf, bOff, enc_layer);
        p1[0] = acc[nt][2] + score_bias<MODE>(r1, col,   hh, slen, tlen, relb, bacc, pmf, bOff, enc_layer);
        p1[1] = acc[nt][3] + score_bias<MODE>(r1, col+1, hh, slen, tlen, relb, bacc, pmf, bOff, enc_layer);
    }
}

// ------------------------- tensor-core P @ V (double-buffered) ------------
__global__ void __launch_bounds__(256) av_tc(
    const float* __restrict__ P, const float* __restrict__ V, float* __restrict__ O)
{
    constexpr int LDA = 40, LDB = 72;
    __shared__ __align__(16) __nv_bfloat16 Ah[2][64*LDA], Al[2][64*LDA];
    __shared__ __align__(16) __nv_bfloat16 Bh[2][32*LDB], Bl[2][32*LDB];

    const int bh = blockIdx.y, b = bh / CH, hh = bh % CH;
    const int q0 = blockIdx.x * 64;
    const int tid = threadIdx.x;
    const int lane = tid & 31, w = tid >> 5;
    const int wm = w & 3, wn = w >> 2;
    const int arow = tid >> 3, ac = (tid & 7) << 2;
    const int brow = tid >> 4, bc = (tid & 15) << 2;

    float4 pa[2];
    float4 pb[2];
    float acc[4][4];
#pragma unroll
    for (int i = 0; i < 4; i++) { acc[i][0]=acc[i][1]=acc[i][2]=acc[i][3]=0.f; }

    auto loadg = [&](int kt) {
#pragma unroll
        for (int it = 0; it < 2; it++)
            pa[it] = *(const float4*)(P + ((size_t)bh*CS + q0 + arow + it*32) * CS + kt*32 + ac);
#pragma unroll
        for (int it = 0; it < 2; it++)
            pb[it] = *(const float4*)(V + (size_t)(b*CS + kt*32 + brow + it*16) * CDM + hh*CDK + bc);
    };
    auto stores = [&](int p) {
#pragma unroll
        for (int it = 0; it < 2; it++) {
            int row = arow + it*32;
            uint2 h4, l4;
            splt4(pa[it], h4, l4);
            *(uint2*)&Ah[p][row*LDA + ac] = h4;
            *(uint2*)&Al[p][row*LDA + ac] = l4;
        }
#pragma unroll
        for (int it = 0; it < 2; it++) {
            int row = brow + it*16;
            uint2 h4, l4;
            splt4(pb[it], h4, l4);
            *(uint2*)&Bh[p][row*LDB + bc] = h4;
            *(uint2*)&Bl[p][row*LDB + bc] = l4;
        }
    };

    loadg(0);
    stores(0);
    __syncthreads();

    for (int kt = 0; kt < CS/32; kt++) {
        const int p = kt & 1;
        const bool more = (kt + 1 < CS/32);
        if (more) loadg(kt + 1);
#pragma unroll
        for (int kh = 0; kh < 2; kh++) {
            unsigned a_h[4], a_l[4];
            const int aoff = (wm*16 + (lane & 15)) * LDA + kh*16 + ((lane >> 4) << 3);
            ldsm4(a_h, &Ah[p][aoff]);
            ldsm4(a_l, &Al[p][aoff]);
            unsigned bhf[8], blf[8];
#pragma unroll
            for (int t2 = 0; t2 < 2; t2++) {
                const int boff = (kh*16 + (lane & 15)) * LDB
                               + wn*32 + t2*16 + ((lane >> 4) << 3);
                ldsm4t(&bhf[t2*4], &Bh[p][boff]);
                ldsm4t(&blf[t2*4], &Bl[p][boff]);
            }
#pragma unroll
            for (int nt = 0; nt < 4; nt++) mma16816(acc[nt], a_h, bhf[2*nt], bhf[2*nt+1]);
#pragma unroll
            for (int nt = 0; nt < 4; nt++) mma16816(acc[nt], a_h, blf[2*nt], blf[2*nt+1]);
#pragma unroll
            for (int nt = 0; nt < 4; nt++) mma16816(acc[nt], a_l, bhf[2*nt], bhf[2*nt+1]);
        }
        if (more) stores(p ^ 1);
        __syncthreads();
    }

    const int g = lane >> 2, qd = lane & 3;
#pragma unroll
    for (int nt = 0; nt < 4; nt++) {
        const int col = hh*CDK + wn*32 + nt*8 + qd*2;
        const size_t r0 = (size_t)(b*CS + q0 + wm*16 + g) * CDM + col;
        const size_t r1 = r0 + (size_t)8 * CDM;
        O[r0] = acc[nt][0]; O[r0+1] = acc[nt][1];
        O[r1] = acc[nt][2]; O[r1+1] = acc[nt][3];
    }
}

// ------------------------- softmax over rows of length 512 ----------------
__global__ void __launch_bounds__(256) softmax_kernel(float* __restrict__ Sc)
{
    __shared__ float sh[8];
    float* row = Sc + (size_t)blockIdx.x * CS;
    const int t = threadIdx.x;
    float v0 = row[t], v1 = row[t + 256];
    float m = fmaxf(v0, v1);
#pragma unroll
    for (int o = 16; o; o >>= 1) m = fmaxf(m, __shfl_xor_sync(0xffffffffu, m, o));
    if ((t & 31) == 0) sh[t >> 5] = m;
    __syncthreads();
    float bm = sh[t & 7];
#pragma unroll
    for (int o = 4; o; o >>= 1) bm = fmaxf(bm, __shfl_xor_sync(0xffffffffu, bm, o));
    float e0 = expf(v0 - bm), e1 = expf(v1 - bm);
    float s = e0 + e1;
#pragma unroll
    for (int o = 16; o; o >>= 1) s += __shfl_xor_sync(0xffffffffu, s, o);
    __syncthreads();
    if ((t & 31) == 0) sh[t >> 5] = s;
    __syncthreads();
    float ts = sh[t & 7];
#pragma unroll
    for (int o = 4; o; o >>= 1) ts += __shfl_xor_sync(0xffffffffu, ts, o);
    float inv = 1.f / ts;
    row[t] = e0 * inv; row[t + 256] = e1 * inv;
}

// ------------------------- RMSNorm (T5) -----------------------------------
__global__ void __launch_bounds__(256) rms_kernel(
    const float* __restrict__ x, const float* __restrict__ w,
    float* __restrict__ out, float scale)
{
    __shared__ float sh[8];
    const int row = blockIdx.x, t = threadIdx.x;
    const float* xr = x + (size_t)row * CDM;
    float v0 = xr[t], v1 = xr[t+256], v2 = xr[t+512];
    float s = v0*v0 + v1*v1 + v2*v2;
#pragma unroll
    for (int o = 16; o; o >>= 1) s += __shfl_xor_sync(0xffffffffu, s, o);
    if ((t & 31) == 0) sh[t >> 5] = s;
    __syncthreads();
    float ts = sh[t & 7];
#pragma unroll
    for (int o = 4; o; o >>= 1) ts += __shfl_xor_sync(0xffffffffu, ts, o);
    float inv = rsqrtf(ts * (1.0f/CDM) + 1e-6f) * scale;
    float* orow = out + (size_t)row * CDM;
    orow[t]     = v0 * inv * w[t];
    orow[t+256] = v1 * inv * w[t+256];
    orow[t+512] = v2 * inv * w[t+512];
}

// ------------------------- elementwise helpers ----------------------------
__global__ void __launch_bounds__(256) embed_gather(
    const float* __restrict__ embed, const int* __restrict__ tok,
    float* __restrict__ out)
{
    int idx = blockIdx.x * 256 + threadIdx.x;
    int r = idx / CDM, c = idx - r * CDM;
    out[idx] = embed[(size_t)tok[r] * CDM + c];
}

__global__ void zero_ch0(float* __restrict__ x)
{
    int r = blockIdx.x * 256 + threadIdx.x;
    if (r < NROWS) x[(size_t)r * CDM] = 0.f;
}

__global__ void init_bacc()
{
    int i = blockIdx.x * 256 + threadIdx.x;
    if (i < CB*CS) g_bacc[i] = 0.f;
}

__global__ void copy_k(const float* __restrict__ src, float* __restrict__ dst)
{
    int i = blockIdx.x * 256 + threadIdx.x;
    dst[i] = src[i];
}

// ------------------------- prune gate -------------------------------------
__global__ void __launch_bounds__(512) gate_kernel(
    const float* __restrict__ x, const float* __restrict__ gumbel,
    const int* __restrict__ src_len, const int* __restrict__ keep,
    float* __restrict__ out_pm, float* __restrict__ out_pp, int layer)
{
    const int b = blockIdx.x, s = threadIdx.x;
    float x0 = x[(size_t)(b*CS + s) * CDM];
    float z = (x0 + gumbel[(b*CL + layer) * CS + s] + 3.0f) * 2.0f;
    float ls = (z >= 0.f) ? -log1pf(expf(-z)) : (z - log1pf(expf(z)));
    float pm = ls + ((layer > 0) ? g_pm[b*CS + s] : 0.f);
    if (s == keep[b]) pm = 0.f;
    g_pm[b*CS + s] = pm;
    g_bacc[b*CS + s] += pm;
    out_pm[(b*CL + layer) * CS + s] = pm;
    out_pp[(b*CL + layer) * CS + s] = expf(pm * 0.125f) * ((s < src_len[b]) ? 1.f : 0.f);
}

// ------------------------- host orchestration -----------------------------
extern "C" void kernel_launch(void* const* d_in, const int* in_sizes, int n_in,
                              void* d_out, int out_size)
{
    const float* embed      = (const float*)d_in[0];
    const float* enc_ln     = (const float*)d_in[1];
    const float* enc_attn_w = (const float*)d_in[2];
    const float* enc_wi     = (const float*)d_in[3];
    const float* enc_wo     = (const float*)d_in[4];
    const float* enc_relb   = (const float*)d_in[5];
    const float* enc_fln    = (const float*)d_in[6];
    const float* dec_ln     = (const float*)d_in[7];
    const float* dec_self_w = (const float*)d_in[8];
    const float* dec_cross_w= (const float*)d_in[9];
    const float* dec_wi     = (const float*)d_in[10];
    const float* dec_wo     = (const float*)d_in[11];
    const float* dec_relb   = (const float*)d_in[12];
    const float* dec_fln    = (const float*)d_in[13];
    const float* gumbel     = (const float*)d_in[14];
    const int*   src_tok    = (const int*)d_in[15];
    const int*   src_len    = (const int*)d_in[16];
    const int*   tgt_tok    = (const int*)d_in[17];
    const int*   tgt_len    = (const int*)d_in[18];
    const int*   keep       = (const int*)d_in[19];

    float* out = (float*)d_out;
    float* out_mem = out;
    float* out_pm  = out + (size_t)CB*CS*CDM;
    float* out_pp  = out_pm + (size_t)CB*CL*CS;
    float* out_log = out_pp + (size_t)CB*CL*CS;

    float *x, *h, *qkv, *o, *mem, *ff, *sc, *bacc, *pm;
    cudaGetSymbolAddress((void**)&x,   g_x);
    cudaGetSymbolAddress((void**)&h,   g_h);
    cudaGetSymbolAddress((void**)&qkv, g_qkv);
    cudaGetSymbolAddress((void**)&o,   g_o);
    cudaGetSymbolAddress((void**)&mem, g_mem);
    cudaGetSymbolAddress((void**)&ff,  g_ff);
    cudaGetSymbolAddress((void**)&sc,  g_sc);
    cudaGetSymbolAddress((void**)&bacc,g_bacc);
    cudaGetSymbolAddress((void**)&pm,  g_pm);

    float* q = qkv;
    float* k = qkv + (size_t)NROWS*CDM;
    float* v = qkv + (size_t)2*NROWS*CDM;
    const long QS = (long)NROWS*CDM;
    const long WS = (long)CDM*CDM;

    const dim3 gQKV(CDM/64, NROWS/64, 3);
    const dim3 gPrj(CDM/64, NROWS/64);
    const dim3 gWi (CDFF/128, NROWS/64);
    const dim3 gLg (CV/128, NROWS/64);
    const dim3 gSc(CS/128, CS/64, CB*CH);
    const dim3 gAv(CS/64, CB*CH);
    const int  nSoft = CB*CH*CS;
    const float inv_sqrt_dm = 0.03608439182435161f;

    init_bacc<<<4, 256>>>();
    embed_gather<<<NROWS*CDM/256, 256>>>(embed, src_tok, x);

    // ---------------- encoder ----------------
    for (int i = 0; i < CL; i++) {
        const float* W = enc_attn_w + (size_t)i*4*CDM*CDM;
        zero_ch0<<<4, 256>>>(x);
        rms_kernel<<<NROWS, 256>>>(x, enc_ln + (size_t)(i*2+0)*CDM, h, 1.f);
        gemm_tc<64,false,false,false,true><<<gQKV, 256>>>(
            h, h, W, WS, qkv, QS, NROWS, CDM, CDM);
        scores_tc<0><<<gSc, 256>>>(q, k, sc, enc_relb, src_len, tgt_len, bacc, pm, i);
        softmax_kernel<<<nSoft, 256>>>(sc);
        av_tc<<<gAv, 256>>>(sc, v, o);
        gemm_tc<64,false,true,false,false><<<gPrj, 256>>>(
            o, o, W + 3*WS, 0, x, 0, NROWS, CDM, CDM);
        rms_kernel<<<NROWS, 256>>>(x, enc_ln + (size_t)(i*2+1)*CDM, h, 1.f);
        gemm_tc<128,false,false,true,false><<<gWi, 256>>>(
            h, h, enc_wi + (size_t)i*CDM*CDFF, 0, ff, 0, NROWS, CDFF, CDM);
        gemm_tc<64,false,true,false,false><<<gPrj, 256>>>(
            ff, ff, enc_wo + (size_t)i*CDFF*CDM, 0, x, 0, NROWS, CDM, CDFF);
        gate_kernel<<<CB, 512>>>(x, gumbel, src_len, keep, out_pm, out_pp, i);
    }
    rms_kernel<<<NROWS, 256>>>(x, enc_fln, mem, 1.f);
    copy_k<<<NROWS*CDM/256, 256>>>(mem, out_mem);

    // ---------------- decoder ----------------
    embed_gather<<<NROWS*CDM/256, 256>>>(embed, tgt_tok, x);
    for (int i = 0; i < CL; i++) {
        const float* Ws = dec_self_w  + (size_t)i*4*CDM*CDM;
        const float* Wc = dec_cross_w + (size_t)i*4*CDM*CDM;
        rms_kernel<<<NROWS, 256>>>(x, dec_ln + (size_t)(i*3+0)*CDM, h, 1.f);
        gemm_tc<64,false,false,false,true><<<gQKV, 256>>>(
            h, h, Ws, WS, qkv, QS, NROWS, CDM, CDM);
        scores_tc<1><<<gSc, 256>>>(q, k, sc, dec_relb, src_len, tgt_len, bacc, pm, 0);
        softmax_kernel<<<nSoft, 256>>>(sc);
        av_tc<<<gAv, 256>>>(sc, v, o);
        gemm_tc<64,false,true,false,false><<<gPrj, 256>>>(
            o, o, Ws + 3*WS, 0, x, 0, NROWS, CDM, CDM);
        rms_kernel<<<NROWS, 256>>>(x, dec_ln + (size_t)(i*3+1)*CDM, h, 1.f);
        gemm_tc<64,false,false,false,true><<<gQKV, 256>>>(
            h, mem, Wc, WS, qkv, QS, NROWS, CDM, CDM);
        scores_tc<2><<<gSc, 256>>>(q, k, sc, dec_relb, src_len, tgt_len, bacc, pm, 0);
        softmax_kernel<<<nSoft, 256>>>(sc);
        av_tc<<<gAv, 256>>>(sc, v, o);
        gemm_tc<64,false,true,false,false><<<gPrj, 256>>>(
            o, o, Wc + 3*WS, 0, x, 0, NROWS, CDM, CDM);
        rms_kernel<<<NROWS, 256>>>(x, dec_ln + (size_t)(i*3+2)*CDM, h, 1.f);
        gemm_tc<128,false,false,true,false><<<gWi, 256>>>(
            h, h, dec_wi + (size_t)i*CDM*CDFF, 0, ff, 0, NROWS, CDFF, CDM);
        gemm_tc<64,false,true,false,false><<<gPrj, 256>>>(
            ff, ff, dec_wo + (size_t)i*CDFF*CDM, 0, x, 0, NROWS, CDM, CDFF);
    }
    rms_kernel<<<NROWS, 256>>>(x, dec_fln, h, inv_sqrt_dm);
    gemm_tc<128,true,false,false,false><<<gLg, 256>>>(
        h, h, embed, 0, out_log, 0, NROWS, CV, CDM);
}

// round 17
// speedup vs baseline: 1.0321x; 1.0128x over previous
// R16 theory (comments only; whole reply is one cuda block).
//
// R15 post-mortem: STS vectorization gained 51 us (9,216 -> 9,165).
// GEMM micro-opts are plateauing (<1% each): the GEMM mainloop is near its
// LDSM+HMMA issue bound. New budget model of the REST of the pipeline:
// softmax is MUFU-bound: 6.3M exp per call at rt_SMSP=8 -> ~40 us/call,
// 36 calls ~= 1.4 ms. Decoder self-attention has a 128-wide sliding
// window: ~75% of its 512 columns are hard-masked (-1e9), so most of the
// scores MMA work, softmax exp work, and av_tc P@V work on those columns
// produces exact zeros.
//
// This round: exact sparsity exploitation, three changes, all bit-exact
// (masked entries underflow to exactly 0 in fp32 either way):
//  1. scores_tc MODE==1: early-out for k-tiles fully outside the causal
//     window (and not containing col 0, which has the past-tgt_len
//     override): write bias-only, skip loads+MMA (~50% of dec-self tiles).
//  2. av_tc<WIN>: for decoder self, iterate only k-chunks intersecting
//     [q0-128, q0+63] plus chunk 0 (col-0 override lives there). Average
//     5.9/16 chunks -> ~63% of dec-self AV work skipped. P is exactly 0.0
//     on skipped chunks (exp underflow), so results are identical.
//  3. softmax: branch-skip expf when v-bm < -1e8 (only true masked
//     entries; exp(-1e9) == 0.0f exactly). Saves MUFU on ~60% of dec-self
//     lanes and padded encoder/cross columns.
//
// Prediction: dur_us 9,165 -> ~8,700-8,900 (-300..450 us); rel_err
// unchanged at 1.973e-5 (transformations exact). If delta < 100 us, the
// attention share was overestimated and the next lever is structural
// (tcgen05 GEMM or layer fusion).

#include <cuda_runtime.h>
#include <cuda_bf16.h>
#include <math.h>

#define CL   12
#define CH   12
#define CDK  64
#define CDM  768
#define CDFF 3072
#define CV   32128
#define CB   2
#define CS   512
#define CT   512
#define NROWS (CB*CS)
#define NEGV (-1e9f)

// ------------------------- device scratch (static, no allocation) ---------
__device__ __align__(16) float g_x  [NROWS*CDM];
__device__ __align__(16) float g_h  [NROWS*CDM];
__device__ __align__(16) float g_qkv[3*NROWS*CDM];
__device__ __align__(16) float g_o  [NROWS*CDM];
__device__ __align__(16) float g_mem[NROWS*CDM];
__device__ __align__(16) float g_ff [NROWS*CDFF];
__device__ __align__(16) float g_sc [(size_t)CB*CH*CS*CS];
__device__ __align__(16) float g_bacc[CB*CS];
__device__ __align__(16) float g_pm  [CB*CS];

// ------------------------- rel-position buckets (exact thresholds) --------
__device__ __forceinline__ int bucket_bi(int q, int k) {
    int n = q - k; int ret = 0;
    if (n < 0) { ret = 16; n = -n; }
    if (n < 8) return ret + n;
    int b;
    if      (n < 12) b = 8;
    else if (n < 16) b = 9;
    else if (n < 23) b = 10;
    else if (n < 32) b = 11;
    else if (n < 46) b = 12;
    else if (n < 64) b = 13;
    else if (n < 91) b = 14;
    else             b = 15;
    return ret + b;
}
__device__ __forceinline__ int bucket_uni(int q, int k) {
    int n = q - k; if (n <= 0) return 0;
    if (n < 16) return n;
    if (n < 19)  return 16;
    if (n < 21)  return 17;
    if (n < 24)  return 18;
    if (n < 27)  return 19;
    if (n < 31)  return 20;
    if (n < 35)  return 21;
    if (n < 40)  return 22;
    if (n < 46)  return 23;
    if (n < 52)  return 24;
    if (n < 59)  return 25;
    if (n < 67)  return 26;
    if (n < 77)  return 27;
    if (n < 87)  return 28;
    if (n < 99)  return 29;
    if (n < 113) return 30;
    return 31;
}

// ------------------------- tensor-core helpers ----------------------------
__device__ __forceinline__ void ldsm4(unsigned* r, const void* p) {
    unsigned a = (unsigned)__cvta_generic_to_shared(p);
    asm volatile("ldmatrix.sync.aligned.m8n8.x4.shared.b16 {%0,%1,%2,%3}, [%4];"
        : "=r"(r[0]), "=r"(r[1]), "=r"(r[2]), "=r"(r[3]) : "r"(a));
}
__device__ __forceinline__ void ldsm4t(unsigned* r, const void* p) {
    unsigned a = (unsigned)__cvta_generic_to_shared(p);
    asm volatile("ldmatrix.sync.aligned.m8n8.x4.trans.shared.b16 {%0,%1,%2,%3}, [%4];"
        : "=r"(r[0]), "=r"(r[1]), "=r"(r[2]), "=r"(r[3]) : "r"(a));
}
__device__ __forceinline__ void mma16816(float* c, const unsigned* a, unsigned b0, unsigned b1) {
    asm volatile("mma.sync.aligned.m16n8k16.row.col.f32.bf16.bf16.f32 "
        "{%0,%1,%2,%3}, {%4,%5,%6,%7}, {%8,%9}, {%0,%1,%2,%3};"
        : "+f"(c[0]), "+f"(c[1]), "+f"(c[2]), "+f"(c[3])
        : "r"(a[0]), "r"(a[1]), "r"(a[2]), "r"(a[3]), "r"(b0), "r"(b1));
}
__device__ __forceinline__ void splt(float x, __nv_bfloat16& h, __nv_bfloat16& l) {
    h = __float2bfloat16_rn(x);
    l = __float2bfloat16_rn(x - __bfloat162float(h));
}
__device__ __forceinline__ void splt2(float a, float b, unsigned& h, unsigned& l) {
    __nv_bfloat162 hh = __floats2bfloat162_rn(a, b);
    float la = a - __bfloat162float(__low2bfloat16(hh));
    float lb = b - __bfloat162float(__high2bfloat16(hh));
    __nv_bfloat162 ll = __floats2bfloat162_rn(la, lb);
    h = *reinterpret_cast<unsigned*>(&hh);
    l = *reinterpret_cast<unsigned*>(&ll);
}
__device__ __forceinline__ void splt4(const float4& v, uint2& h, uint2& l) {
    splt2(v.x, v.y, h.x, l.x);
    splt2(v.z, v.w, h.y, l.y);
}

// ------------------------- split-bf16 tensor GEMM (double-buffered) -------
template<int BN, bool NT, bool ADD, bool RELU, bool BATCH>
__global__ void __launch_bounds__(256) gemm_tc(
    const float* __restrict__ A0, const float* __restrict__ A1,
    const float* __restrict__ Bb, long bStride,
    float* __restrict__ Cb, long cStride,
    int M, int N, int K)
{
    constexpr int LDA = 40;
    constexpr int LDB = BN + 8;
    constexpr int NT8 = BN / 16;
    constexpr int PB  = BN / 32;

    __shared__ __align__(16) __nv_bfloat16 Ah[2][64*LDA], Al[2][64*LDA];
    __shared__ __align__(16) __nv_bfloat16 Bh[2][32*LDB], Bl[2][32*LDB];

    const int tid  = threadIdx.x;
    const int z    = BATCH ? blockIdx.z : 0;
    const float* A = (BATCH && z > 0) ? A1 : A0;
    const float* B = Bb + (size_t)z * bStride;
    float*       C = Cb + (size_t)z * cStride;
    const int m0 = blockIdx.y * 64;
    const int n0 = blockIdx.x * BN;
    const int nk = K >> 5;

    const int lane = tid & 31, w = tid >> 5;
    const int wm = w & 3, wn = w >> 2;
    const int arow = tid >> 3, ac = (tid & 7) << 2;

    float4 pa[2];
    float4 pb[PB];

    float acc[NT8][4];
#pragma unroll
    for (int i = 0; i < NT8; i++) { acc[i][0]=acc[i][1]=acc[i][2]=acc[i][3]=0.f; }

    auto loadg = [&](int kt) {
#pragma unroll
        for (int it = 0; it < 2; it++)
            pa[it] = *(const float4*)(A + (size_t)(m0 + arow + it*32) * K + kt*32 + ac);
        if (NT) {
#pragma unroll
            for (int it = 0; it < PB; it++) {
                int idx = tid + it*256;
                int n = idx >> 3, kq = (idx & 7) << 2;
                pb[it] = *(const float4*)(B + (size_t)(n0 + n) * K + kt*32 + kq);
            }
        } else {
#pragma unroll
            for (int it = 0; it < PB; it++) {
                int idx = tid + it*256;
                int br = idx / (BN/4), bc = (idx % (BN/4)) * 4;
                pb[it] = *(const float4*)(B + (size_t)(kt*32 + br) * N + n0 + bc);
            }
        }
    };
    auto stores = [&](int p) {
#pragma unroll
        for (int it = 0; it < 2; it++) {
            int row = arow + it*32;
            uint2 h4, l4;
            splt4(pa[it], h4, l4);
            *(uint2*)&Ah[p][row*LDA + ac] = h4;
            *(uint2*)&Al[p][row*LDA + ac] = l4;
        }
        if (NT) {
#pragma unroll
            for (int it = 0; it < PB; it++) {
                int idx = tid + it*256;
                int n = idx >> 3, kq = (idx & 7) << 2;
                float xs[4] = {pb[it].x, pb[it].y, pb[it].z, pb[it].w};
#pragma unroll
                for (int j = 0; j < 4; j++)
                    splt(xs[j], Bh[p][(kq+j)*LDB + n], Bl[p][(kq+j)*LDB + n]);
            }
        } else {
#pragma unroll
            for (int it = 0; it < PB; it++) {
                int idx = tid + it*256;
                int br = idx / (BN/4), bc = (idx % (BN/4)) * 4;
                uint2 h4, l4;
                splt4(pb[it], h4, l4);
                *(uint2*)&Bh[p][br*LDB + bc] = h4;
                *(uint2*)&Bl[p][br*LDB + bc] = l4;
            }
        }
    };

    loadg(0);
    stores(0);
    __syncthreads();

    for (int kt = 0; kt < nk; kt++) {
        const int p = kt & 1;
        const bool more = (kt + 1 < nk);
        if (more) loadg(kt + 1);
#pragma unroll
        for (int kh = 0; kh < 2; kh++) {
            unsigned a_h[4], a_l[4];
            const int aoff = (wm*16 + (lane & 15)) * LDA + kh*16 + ((lane >> 4) << 3);
            ldsm4(a_h, &Ah[p][aoff]);
            ldsm4(a_l, &Al[p][aoff]);
            unsigned b_h[NT8*2], b_l[NT8*2];
#pragma unroll
            for (int t2 = 0; t2 < NT8/2; t2++) {
                const int boff = (kh*16 + (lane & 15)) * LDB
                               + wn*(BN/2) + t2*16 + ((lane >> 4) << 3);
                ldsm4t(&b_h[t2*4], &Bh[p][boff]);
                ldsm4t(&b_l[t2*4], &Bl[p][boff]);
            }
#pragma unroll
            for (int nt = 0; nt < NT8; nt++) mma16816(acc[nt], a_h, b_h[2*nt], b_h[2*nt+1]);
#pragma unroll
            for (int nt = 0; nt < NT8; nt++) mma16816(acc[nt], a_h, b_l[2*nt], b_l[2*nt+1]);
#pragma unroll
            for (int nt = 0; nt < NT8; nt++) mma16816(acc[nt], a_l, b_h[2*nt], b_h[2*nt+1]);
        }
        if (more) stores(p ^ 1);
        __syncthreads();
    }

    const int g = lane >> 2, qd = lane & 3;
#pragma unroll
    for (int nt = 0; nt < NT8; nt++) {
        const int col = n0 + wn*(BN/2) + nt*8 + qd*2;
        const int r0  = m0 + wm*16 + g;
        size_t i0 = (size_t)r0 * N + col;
        size_t i1 = i0 + (size_t)8 * N;
        float v0 = acc[nt][0], v1 = acc[nt][1], v2 = acc[nt][2], v3 = acc[nt][3];
        if (ADD) { v0 += C[i0]; v1 += C[i0+1]; v2 += C[i1]; v3 += C[i1+1]; }
        if (RELU) { v0 = fmaxf(v0,0.f); v1 = fmaxf(v1,0.f); v2 = fmaxf(v2,0.f); v3 = fmaxf(v3,0.f); }
        C[i0] = v0; C[i0+1] = v1; C[i1] = v2; C[i1+1] = v3;
    }
}

// ------------------------- bias (shared by score kernels) ------------------
template<int MODE>
__device__ __forceinline__ float score_bias(
    int qg, int kg, int hh, int slen, int tlen,
    const float* __restrict__ relb,
    const float* __restrict__ bacc, const float* __restrict__ pmf,
    int bOff, int enc_layer)
{
    if (MODE == 0) {
        if (enc_layer > 0 && qg == kg) return 0.f;
        return relb[bucket_bi(qg, kg) * CH + hh]
             + ((kg < slen) ? 0.f : NEGV)
             + bacc[bOff + qg] + bacc[bOff + kg];
    } else if (MODE == 1) {
        float tm;
        if (kg == 0 && qg >= tlen) tm = 0.f;
        else tm = ((kg < slen) ? 0.f : NEGV)
                + (((kg <= qg) && (kg >= qg - 128)) ? 0.f : NEGV);
        return relb[bucket_uni(qg, kg) * CH + hh] + tm;
    } else {
        return ((kg < slen) ? 0.f : NEGV) + pmf[bOff + kg];
    }
}

// ------------------------- tensor-core attention scores -------------------
template<int MODE>
__global__ void __launch_bounds__(256) scores_tc(
    const float* __restrict__ Q, const float* __restrict__ Km,
    float* __restrict__ Sc, const float* __restrict__ relb,
    const int* __restrict__ src_len, const int* __restrict__ tgt_len,
    const float* __restrict__ bacc, const float* __restrict__ pmf,
    int enc_layer)
{
    constexpr int LDA = 72, LDB = 136;
    __shared__ __align__(16) __nv_bfloat16 Ah[64*LDA], Al[64*LDA];
    __shared__ __align__(16) __nv_bfloat16 Bh[64*LDB], Bl[64*LDB];

    const int bh = blockIdx.z, b = bh / CH, hh = bh % CH;
    const int q0 = blockIdx.y * 64, k0 = blockIdx.x * 128;
    const int tid = threadIdx.x;
    const int lane = tid & 31, w = tid >> 5;
    const int wm = w & 3, wn = w >> 2;
    const int g = lane >> 2, qd = lane & 3;

    // exact early-out for decoder-self tiles fully outside the causal
    // window (future tiles, or far-past tiles not containing column 0):
    // all their scores are dominated by -1e9 masks; QK dot is irrelevant
    // because exp underflows to exactly 0 either way.
    if (MODE == 1) {
        const bool future = (k0 > q0 + 63);
        const bool past   = (k0 != 0) && (k0 + 127 < q0 - 128);
        if (future || past) {
            const int slen = src_len[b];
            const int tlen = tgt_len[b];
            const int bOff = b * CS;
#pragma unroll
            for (int nt = 0; nt < 8; nt++) {
                const int col = k0 + wn*64 + nt*8 + qd*2;
                const int r0  = q0 + wm*16 + g;
                const int r1  = r0 + 8;
                float* p0 = Sc + ((size_t)bh * CS + r0) * CS + col;
                float* p1 = Sc + ((size_t)bh * CS + r1) * CS + col;
                p0[0] = score_bias<MODE>(r0, col,   hh, slen, tlen, relb, bacc, pmf, bOff, 0);
                p0[1] = score_bias<MODE>(r0, col+1, hh, slen, tlen, relb, bacc, pmf, bOff, 0);
                p1[0] = score_bias<MODE>(r1, col,   hh, slen, tlen, relb, bacc, pmf, bOff, 0);
                p1[1] = score_bias<MODE>(r1, col+1, hh, slen, tlen, relb, bacc, pmf, bOff, 0);
            }
            return;
        }
    }

#pragma unroll
    for (int it = 0; it < 4; it++) {
        int idx = tid + it*256;
        int row = idx >> 4, c = (idx & 15) << 2;
        float4 a = *(const float4*)(Q + (size_t)(b*CS + q0 + row) * CDM + hh*CDK + c);
        uint2 h4, l4;
        splt4(a, h4, l4);
        *(uint2*)&Ah[row*LDA + c] = h4;
        *(uint2*)&Al[row*LDA + c] = l4;
    }
#pragma unroll
    for (int it = 0; it < 8; it++) {
        int idx = tid + it*256;
        int n = idx >> 4, c = (idx & 15) << 2;
        float4 kv = *(const float4*)(Km + (size_t)(b*CS + k0 + n) * CDM + hh*CDK + c);
        splt(kv.x, Bh[(c+0)*LDB + n], Bl[(c+0)*LDB + n]);
        splt(kv.y, Bh[(c+1)*LDB + n], Bl[(c+1)*LDB + n]);
        splt(kv.z, Bh[(c+2)*LDB + n], Bl[(c+2)*LDB + n]);
        splt(kv.w, Bh[(c+3)*LDB + n], Bl[(c+3)*LDB + n]);
    }
    __syncthreads();

    float acc[8][4];
#pragma unroll
    for (int i = 0; i < 8; i++) { acc[i][0]=acc[i][1]=acc[i][2]=acc[i][3]=0.f; }

#pragma unroll
    for (int kh = 0; kh < 4; kh++) {
        unsigned a_h[4], a_l[4];
        const int aoff = (wm*16 + (lane & 15)) * LDA + kh*16 + ((lane >> 4) << 3);
        ldsm4(a_h, &Ah[aoff]);
        ldsm4(a_l, &Al[aoff]);
        unsigned bhf[16], blf[16];
#pragma unroll
        for (int t2 = 0; t2 < 4; t2++) {
            const int boff = (kh*16 + (lane & 15)) * LDB
                           + wn*64 + t2*16 + ((lane >> 4) << 3);
            ldsm4t(&bhf[t2*4], &Bh[boff]);
            ldsm4t(&blf[t2*4], &Bl[boff]);
        }
#pragma unroll
        for (int nt = 0; nt < 8; nt++) mma16816(acc[nt], a_h, bhf[2*nt], bhf[2*nt+1]);
#pragma unroll
        for (int nt = 0; nt < 8; nt++) mma16816(acc[nt], a_h, blf[2*nt], blf[2*nt+1]);
#pragma unroll
        for (int nt = 0; nt < 8; nt++) mma16816(acc[nt], a_l, bhf[2*nt], bhf[2*nt+1]);
    }

    const int slen = src_len[b];
    const int tlen = (MODE == 1) ? tgt_len[b] : 0;
    const int bOff = b * CS;
#pragma unroll
    for (int nt = 0; nt < 8; nt++) {
        const int col = k0 + wn*64 + nt*8 + qd*2;
        const int r0  = q0 + wm*16 + g;
        const int r1  = r0 + 8;
        float* p0 = Sc + ((size_t)bh * CS + r0) * CS + col;
        float* p1 = Sc + ((size_t)bh * CS + r1) * CS + col;
        p0[0] = acc[nt][0] + score_bias<MODE>(r0, col,   hh, slen, tlen, relb, bacc, pmf, bOff, enc_layer);
        p0[1] = acc[nt][1] + score_bias<MODE>(r0, col+1, hh, slen, tlen, relb, bacc, pmf, bOff, enc_layer);
        p1[0] = acc[nt][2] + score_bias<MODE>(r1, col,   hh, slen, tlen, relb, bacc, pmf, bOff, enc_layer);
        p1[1] = acc[nt][3] + score_bias<MODE>(r1, col+1, hh, slen, tlen, relb, bacc, pmf, bOff, enc_layer);
    }
}

// ------------------------- tensor-core P @ V (double-buffered) ------------
// WIN=true (decoder self): only k-chunks intersecting [q0-128, q0+63] plus
// chunk 0 contribute (P is exactly 0.0 elsewhere).
template<bool WIN>
__global__ void __launch_bounds__(256) av_tc(
    const float* __restrict__ P, const float* __restrict__ V, float* __restrict__ O)
{
    constexpr int LDA = 40, LDB = 72;
    __shared__ __align__(16) __nv_bfloat16 Ah[2][64*LDA], Al[2][64*LDA];
    __shared__ __align__(16) __nv_bfloat16 Bh[2][32*LDB], Bl[2][32*LDB];

    const int bh = blockIdx.y, b = bh / CH, hh = bh % CH;
    const int q0 = blockIdx.x * 64;
    const int tid = threadIdx.x;
    const int lane = tid & 31, w = tid >> 5;
    const int wm = w & 3, wn = w >> 2;
    const int arow = tid >> 3, ac = (tid & 7) << 2;
    const int brow = tid >> 4, bc = (tid & 15) << 2;

    int seq[17];
    int ns = 0;
    if (WIN) {
        int lo = q0 - 128; if (lo < 0) lo = 0;
        const int ktLo = lo >> 5;
        const int ktHi = (q0 + 63) >> 5;
        if (ktLo > 0) seq[ns++] = 0;
        for (int kt = ktLo; kt <= ktHi; kt++) seq[ns++] = kt;
    } else {
        for (int kt = 0; kt < CS/32; kt++) seq[ns++] = kt;
    }

    float4 pa[2];
    float4 pb[2];
    float acc[4][4];
#pragma unroll
    for (int i = 0; i < 4; i++) { acc[i][0]=acc[i][1]=acc[i][2]=acc[i][3]=0.f; }

    auto loadg = [&](int kt) {
#pragma unroll
        for (int it = 0; it < 2; it++)
            pa[it] = *(const float4*)(P + ((size_t)bh*CS + q0 + arow + it*32) * CS + kt*32 + ac);
#pragma unroll
        for (int it = 0; it < 2; it++)
            pb[it] = *(const float4*)(V + (size_t)(b*CS + kt*32 + brow + it*16) * CDM + hh*CDK + bc);
    };
    auto stores = [&](int p) {
#pragma unroll
        for (int it = 0; it < 2; it++) {
            int row = arow + it*32;
            uint2 h4, l4;
            splt4(pa[it], h4, l4);
            *(uint2*)&Ah[p][row*LDA + ac] = h4;
            *(uint2*)&Al[p][row*LDA + ac] = l4;
        }
#pragma unroll
        for (int it = 0; it < 2; it++) {
            int row = brow + it*16;
            uint2 h4, l4;
            splt4(pb[it], h4, l4);
            *(uint2*)&Bh[p][row*LDB + bc] = h4;
            *(uint2*)&Bl[p][row*LDB + bc] = l4;
        }
    };

    loadg(seq[0]);
    stores(0);
    __syncthreads();

    for (int i = 0; i < ns; i++) {
        const int p = i & 1;
        const bool more = (i + 1 < ns);
        if (more) loadg(seq[i + 1]);
#pragma unroll
        for (int kh = 0; kh < 2; kh++) {
            unsigned a_h[4], a_l[4];
            const int aoff = (wm*16 + (lane & 15)) * LDA + kh*16 + ((lane >> 4) << 3);
            ldsm4(a_h, &Ah[p][aoff]);
            ldsm4(a_l, &Al[p][aoff]);
            unsigned bhf[8], blf[8];
#pragma unroll
            for (int t2 = 0; t2 < 2; t2++) {
                const int boff = (kh*16 + (lane & 15)) * LDB
                               + wn*32 + t2*16 + ((lane >> 4) << 3);
                ldsm4t(&bhf[t2*4], &Bh[p][boff]);
                ldsm4t(&blf[t2*4], &Bl[p][boff]);
            }
#pragma unroll
            for (int nt = 0; nt < 4; nt++) mma16816(acc[nt], a_h, bhf[2*nt], bhf[2*nt+1]);
#pragma unroll
            for (int nt = 0; nt < 4; nt++) mma16816(acc[nt], a_h, blf[2*nt], blf[2*nt+1]);
#pragma unroll
            for (int nt = 0; nt < 4; nt++) mma16816(acc[nt], a_l, bhf[2*nt], bhf[2*nt+1]);
        }
        if (more) stores(p ^ 1);
        __syncthreads();
    }

    const int g = lane >> 2, qd = lane & 3;
#pragma unroll
    for (int nt = 0; nt < 4; nt++) {
        const int col = hh*CDK + wn*32 + nt*8 + qd*2;
        const size_t r0 = (size_t)(b*CS + q0 + wm*16 + g) * CDM + col;
        const size_t r1 = r0 + (size_t)8 * CDM;
        O[r0] = acc[nt][0]; O[r0+1] = acc[nt][1];
        O[r1] = acc[nt][2]; O[r1+1] = acc[nt][3];
    }
}

// ------------------------- softmax over rows of length 512 ----------------
__global__ void __launch_bounds__(256) softmax_kernel(float* __restrict__ Sc)
{
    __shared__ float sh[8];
    float* row = Sc + (size_t)blockIdx.x * CS;
    const int t = threadIdx.x;
    float v0 = row[t], v1 = row[t + 256];
    float m = fmaxf(v0, v1);
#pragma unroll
    for (int o = 16; o; o >>= 1) m = fmaxf(m, __shfl_xor_sync(0xffffffffu, m, o));
    if ((t & 31) == 0) sh[t >> 5] = m;
    __syncthreads();
    float bm = sh[t & 7];
#pragma unroll
    for (int o = 4; o; o >>= 1) bm = fmaxf(bm, __shfl_xor_sync(0xffffffffu, bm, o));
    // masked entries sit at ~-1e9: exp underflows to exactly 0, so branch
    // around the MUFU work for them (bit-exact result).
    float e0 = 0.f, e1 = 0.f;
    if (v0 - bm > -1.0e8f) e0 = expf(v0 - bm);
    if (v1 - bm > -1.0e8f) e1 = expf(v1 - bm);
    float s = e0 + e1;
#pragma unroll
    for (int o = 16; o; o >>= 1) s += __shfl_xor_sync(0xffffffffu, s, o);
    __syncthreads();
    if ((t & 31) == 0) sh[t >> 5] = s;
    __syncthreads();
    float ts = sh[t & 7];
#pragma unroll
    for (int o = 4; o; o >>= 1) ts += __shfl_xor_sync(0xffffffffu, ts, o);
    float inv = 1.f / ts;
    row[t] = e0 * inv; row[t + 256] = e1 * inv;
}

// ------------------------- RMSNorm (T5) -----------------------------------
__global__ void __launch_bounds__(256) rms_kernel(
    const float* __restrict__ x, const float* __restrict__ w,
    float* __restrict__ out, float scale)
{
    __shared__ float sh[8];
    const int row = blockIdx.x, t = threadIdx.x;
    const float* xr = x + (size_t)row * CDM;
    float v0 = xr[t], v1 = xr[t+256], v2 = xr[t+512];
    float s = v0*v0 + v1*v1 + v2*v2;
#pragma unroll
    for (int o = 16; o; o >>= 1) s += __shfl_xor_sync(0xffffffffu, s, o);
    if ((t & 31) == 0) sh[t >> 5] = s;
    __syncthreads();
    float ts = sh[t & 7];
#pragma unroll
    for (int o = 4; o; o >>= 1) ts += __shfl_xor_sync(0xffffffffu, ts, o);
    float inv = rsqrtf(ts * (1.0f/CDM) + 1e-6f) * scale;
    float* orow = out + (size_t)row * CDM;
    orow[t]     = v0 * inv * w[t];
    orow[t+256] = v1 * inv * w[t+256];
    orow[t+512] = v2 * inv * w[t+512];
}

// ------------------------- elementwise helpers ----------------------------
__global__ void __launch_bounds__(256) embed_gather(
    const float* __restrict__ embed, const int* __restrict__ tok,
    float* __restrict__ out)
{
    int idx = blockIdx.x * 256 + threadIdx.x;
    int r = idx / CDM, c = idx - r * CDM;
    out[idx] = embed[(size_t)tok[r] * CDM + c];
}

__global__ void zero_ch0(float* __restrict__ x)
{
    int r = blockIdx.x * 256 + threadIdx.x;
    if (r < NROWS) x[(size_t)r * CDM] = 0.f;
}

__global__ void init_bacc()
{
    int i = blockIdx.x * 256 + threadIdx.x;
    if (i < CB*CS) g_bacc[i] = 0.f;
}

__global__ void copy_k(const float* __restrict__ src, float* __restrict__ dst)
{
    int i = blockIdx.x * 256 + threadIdx.x;
    dst[i] = src[i];
}

// ------------------------- prune gate -------------------------------------
__global__ void __launch_bounds__(512) gate_kernel(
    const float* __restrict__ x, const float* __restrict__ gumbel,
    const int* __restrict__ src_len, const int* __restrict__ keep,
    float* __restrict__ out_pm, float* __restrict__ out_pp, int layer)
{
    const int b = blockIdx.x, s = threadIdx.x;
    float x0 = x[(size_t)(b*CS + s) * CDM];
    float z = (x0 + gumbel[(b*CL + layer) * CS + s] + 3.0f) * 2.0f;
    float ls = (z >= 0.f) ? -log1pf(expf(-z)) : (z - log1pf(expf(z)));
    float pm = ls + ((layer > 0) ? g_pm[b*CS + s] : 0.f);
    if (s == keep[b]) pm = 0.f;
    g_pm[b*CS + s] = pm;
    g_bacc[b*CS + s] += pm;
    out_pm[(b*CL + layer) * CS + s] = pm;
    out_pp[(b*CL + layer) * CS + s] = expf(pm * 0.125f) * ((s < src_len[b]) ? 1.f : 0.f);
}

// ------------------------- host orchestration -----------------------------
extern "C" void kernel_launch(void* const* d_in, const int* in_sizes, int n_in,
                              void* d_out, int out_size)
{
    const float* embed      = (const float*)d_in[0];
    const float* enc_ln     = (const float*)d_in[1];
    const float* enc_attn_w = (const float*)d_in[2];
    const float* enc_wi     = (const float*)d_in[3];
    const float* enc_wo     = (const float*)d_in[4];
    const float* enc_relb   = (const float*)d_in[5];
    const float* enc_fln    = (const float*)d_in[6];
    const float* dec_ln     = (const float*)d_in[7];
    const float* dec_self_w = (const float*)d_in[8];
    const float* dec_cross_w= (const float*)d_in[9];
    const float* dec_wi     = (const float*)d_in[10];
    const float* dec_wo     = (const float*)d_in[11];
    const float* dec_relb   = (const float*)d_in[12];
    const float* dec_fln    = (const float*)d_in[13];
    const float* gumbel     = (const float*)d_in[14];
    const int*   src_tok    = (const int*)d_in[15];
    const int*   src_len    = (const int*)d_in[16];
    const int*   tgt_tok    = (const int*)d_in[17];
    const int*   tgt_len    = (const int*)d_in[18];
    const int*   keep       = (const int*)d_in[19];

    float* out = (float*)d_out;
    float* out_mem = out;
    float* out_pm  = out + (size_t)CB*CS*CDM;
    float* out_pp  = out_pm + (size_t)CB*CL*CS;
    float* out_log = out_pp + (size_t)CB*CL*CS;

    float *x, *h, *qkv, *o, *mem, *ff, *sc, *bacc, *pm;
    cudaGetSymbolAddress((void**)&x,   g_x);
    cudaGetSymbolAddress((void**)&h,   g_h);
    cudaGetSymbolAddress((void**)&qkv, g_qkv);
    cudaGetSymbolAddress((void**)&o,   g_o);
    cudaGetSymbolAddress((void**)&mem, g_mem);
    cudaGetSymbolAddress((void**)&ff,  g_ff);
    cudaGetSymbolAddress((void**)&sc,  g_sc);
    cudaGetSymbolAddress((void**)&bacc,g_bacc);
    cudaGetSymbolAddress((void**)&pm,  g_pm);

    float* q = qkv;
    float* k = qkv + (size_t)NROWS*CDM;
    float* v = qkv + (size_t)2*NROWS*CDM;
    const long QS = (long)NROWS*CDM;
    const long WS = (long)CDM*CDM;

    const dim3 gQKV(CDM/64, NROWS/64, 3);
    const dim3 gPrj(CDM/64, NROWS/64);
    const dim3 gWi (CDFF/128, NROWS/64);
    const dim3 gLg (CV/128, NROWS/64);
    const dim3 gSc(CS/128, CS/64, CB*CH);
    const dim3 gAv(CS/64, CB*CH);
    const int  nSoft = CB*CH*CS;
    const float inv_sqrt_dm = 0.03608439182435161f;

    init_bacc<<<4, 256>>>();
    embed_gather<<<NROWS*CDM/256, 256>>>(embed, src_tok, x);

    // ---------------- encoder ----------------
    for (int i = 0; i < CL; i++) {
        const float* W = enc_attn_w + (size_t)i*4*CDM*CDM;
        zero_ch0<<<4, 256>>>(x);
        rms_kernel<<<NROWS, 256>>>(x, enc_ln + (size_t)(i*2+0)*CDM, h, 1.f);
        gemm_tc<64,false,false,false,true><<<gQKV, 256>>>(
            h, h, W, WS, qkv, QS, NROWS, CDM, CDM);
        scores_tc<0><<<gSc, 256>>>(q, k, sc, enc_relb, src_len, tgt_len, bacc, pm, i);
        softmax_kernel<<<nSoft, 256>>>(sc);
        av_tc<false><<<gAv, 256>>>(sc, v, o);
        gemm_tc<64,false,true,false,false><<<gPrj, 256>>>(
            o, o, W + 3*WS, 0, x, 0, NROWS, CDM, CDM);
        rms_kernel<<<NROWS, 256>>>(x, enc_ln + (size_t)(i*2+1)*CDM, h, 1.f);
        gemm_tc<128,false,false,true,false><<<gWi, 256>>>(
            h, h, enc_wi + (size_t)i*CDM*CDFF, 0, ff, 0, NROWS, CDFF, CDM);
        gemm_tc<64,false,true,false,false><<<gPrj, 256>>>(
            ff, ff, enc_wo + (size_t)i*CDFF*CDM, 0, x, 0, NROWS, CDM, CDFF);
        gate_kernel<<<CB, 512>>>(x, gumbel, src_len, keep, out_pm, out_pp, i);
    }
    rms_kernel<<<NROWS, 256>>>(x, enc_fln, mem, 1.f);
    copy_k<<<NROWS*CDM/256, 256>>>(mem, out_mem);

    // ---------------- decoder ----------------
    embed_gather<<<NROWS*CDM/256, 256>>>(embed, tgt_tok, x);
    for (int i = 0; i < CL; i++) {
        const float* Ws = dec_self_w  + (size_t)i*4*CDM*CDM;
        const float* Wc = dec_cross_w + (size_t)i*4*CDM*CDM;
        rms_kernel<<<NROWS, 256>>>(x, dec_ln + (size_t)(i*3+0)*CDM, h, 1.f);
        gemm_tc<64,false,false,false,true><<<gQKV, 256>>>(
            h, h, Ws, WS, qkv, QS, NROWS, CDM, CDM);
        scores_tc<1><<<gSc, 256>>>(q, k, sc, dec_relb, src_len, tgt_len, bacc, pm, 0);
        softmax_kernel<<<nSoft, 256>>>(sc);
        av_tc<true><<<gAv, 256>>>(sc, v, o);
        gemm_tc<64,false,true,false,false><<<gPrj, 256>>>(
            o, o, Ws + 3*WS, 0, x, 0, NROWS, CDM, CDM);
        rms_kernel<<<NROWS, 256>>>(x, dec_ln + (size_t)(i*3+1)*CDM, h, 1.f);
        gemm_tc<64,false,false,false,true><<<gQKV, 256>>>(
            h, mem, Wc, WS, qkv, QS, NROWS, CDM, CDM);
        scores_tc<2><<<gSc, 256>>>(q, k, sc, dec_relb, src_len, tgt_len, bacc, pm, 0);
        softmax_kernel<<<nSoft, 256>>>(sc);
        av_tc<false><<<gAv, 256>>>(sc, v, o);
        gemm_tc<64,false,true,false,false><<<gPrj, 256>>>(
            o, o, Wc + 3*WS, 0, x, 0, NROWS, CDM, CDM);
        rms_kernel<<<NROWS, 256>>>(x, dec_ln + (size_t)(i*3+2)*CDM, h, 1.f);
        gemm_tc<128,false,false,true,false><<<gWi, 256>>>(
            h, h, dec_wi + (size_t)i*CDM*CDFF, 0, ff, 0, NROWS, CDFF, CDM);
        gemm_tc<64,false,true,false,false><<<gPrj, 256>>>(
            ff, ff, dec_wo + (size_t)i*CDFF*CDM, 0, x, 0, NROWS, CDM, CDFF);
    }
    rms_kernel<<<NROWS, 256>>>(x, dec_fln, h, inv_sqrt_dm);
    gemm_tc<128,true,false,false,false><<<gLg, 256>>>(
        h, h, embed, 0, out_log, 0, NROWS, CV, CDM);
}